// round 10
// baseline (speedup 1.0000x reference)
#include <cuda_runtime.h>
#include <cuda_bf16.h>
#include <stdint.h>

#define NT 512
#define NCTA 148
#define HCTA 74

// ---------------- math helpers ----------------
__device__ __forceinline__ float fsigm(float x) { return __fdividef(1.0f, 1.0f + __expf(-x)); }
__device__ __forceinline__ float ftanh(float x) {
    return 1.0f - __fdividef(2.0f, __expf(2.0f * x) + 1.0f);
}
__device__ __forceinline__ uint32_t cvt_bf16x2(float x, float y) {   // lo=x, hi=y
    uint32_t r;
    asm("cvt.rn.bf16x2.f32 %0, %1, %2;" : "=r"(r) : "f"(y), "f"(x));
    return r;
}
__device__ __forceinline__ void split2f(float a, float b, uint32_t& hi, uint32_t& lo) {
    hi = cvt_bf16x2(a, b);
    float af = __uint_as_float(hi << 16);
    float bf = __uint_as_float(hi & 0xffff0000u);
    lo = cvt_bf16x2(a - af, b - bf);
}
__device__ __forceinline__ uint32_t smem_u32(const void* p) {
    uint32_t a;
    asm("{ .reg .u64 t; cvta.to.shared.u64 t, %1; cvt.u32.u64 %0, t; }" : "=r"(a) : "l"(p));
    return a;
}

// ---------------- mma + ldmatrix ----------------
__device__ __forceinline__ void mma16816(float* c, const uint32_t* a, const uint32_t* b) {
    asm volatile(
        "mma.sync.aligned.m16n8k16.row.col.f32.bf16.bf16.f32 "
        "{%0,%1,%2,%3}, {%4,%5,%6,%7}, {%8,%9}, {%0,%1,%2,%3};"
        : "+f"(c[0]), "+f"(c[1]), "+f"(c[2]), "+f"(c[3])
        : "r"(a[0]), "r"(a[1]), "r"(a[2]), "r"(a[3]), "r"(b[0]), "r"(b[1]));
}
__device__ __forceinline__ void ldsm4(uint32_t* d, uint32_t addr) {
    asm volatile("ldmatrix.sync.aligned.m8n8.x4.shared.b16 {%0,%1,%2,%3}, [%4];"
                 : "=r"(d[0]), "=r"(d[1]), "=r"(d[2]), "=r"(d[3]) : "r"(addr));
}

// ---------------- weight scratch: swizzled [64][64] bf16 tiles, 8KB each ------
// half-index for (row n, col k): n*64 + ((k>>3 ^ (n&7))<<3) + (k&7)
#define TILE_B 8192
#define TILE_H 4096
__device__ __align__(16) __nv_bfloat16 g_wt[2][20][TILE_H];

__global__ void convert_weights_kernel(
    const float* __restrict__ fc1a, const float* __restrict__ wiha, const float* __restrict__ whha,
    const float* __restrict__ fc1b, const float* __restrict__ wihb, const float* __restrict__ whhb)
{
    int tid = blockIdx.x * blockDim.x + threadIdx.x;
    int stride = gridDim.x * blockDim.x;
    for (int s = 0; s < 2; ++s) {
        const float* fc1 = s ? fc1b : fc1a;
        const float* wih = s ? wihb : wiha;
        const float* whh = s ? whhb : whha;
        for (int e = tid; e < 40960; e += stride) {
            float v; int th, tl, n, k;
            if (e < 16384) {                        // fc1 [64,256] -> tiles 0..7
                n = e >> 8; int kf = e & 255; int kc = kf >> 6; k = kf & 63;
                v = fc1[e]; th = kc; tl = 4 + kc;
            } else if (e < 28672) {                 // wih [192,64] -> tiles 8..13
                int e2 = e - 16384, j = e2 >> 6; k = e2 & 63; int gg = j >> 6; n = j & 63;
                v = wih[e2]; th = 8 + gg; tl = 11 + gg;
            } else {                                // whh [192,64] -> tiles 14..19
                int e2 = e - 28672, j = e2 >> 6; k = e2 & 63; int gg = j >> 6; n = j & 63;
                v = whh[e2]; th = 14 + gg; tl = 17 + gg;
            }
            uint32_t off = n * 64 + (((k >> 3) ^ (n & 7)) << 3) + (k & 7);
            __nv_bfloat16 hi = __float2bfloat16(v);
            __nv_bfloat16 lo = __float2bfloat16(v - __bfloat162float(hi));
            g_wt[s][th][off] = hi;
            g_wt[s][tl][off] = lo;
        }
    }
}

// ---------------- smem layout (bytes) ----------------
#define SM_W    0                 // 20 tiles = 163840
#define SM_X    163840            // 32KB: Phase B ping-pong (2x16KB) / X planes / VP @+24K
#define SM_HHI  196608            // [128 rows][128 B]
#define SM_HLO  212992
#define SM_BIH  229376            // float[192]
#define SM_BHH  230144
#define SM_B1   230912
#define SM_W2   231168
#define SMEM_TOTAL 231424

__global__ __launch_bounds__(NT, 1)
void gru_hmma_kernel(
    const float* __restrict__ obs, const float* __restrict__ h1, const float* __restrict__ h2,
    const int* __restrict__ mask,
    const float* __restrict__ bih1, const float* __restrict__ bhh1,
    const float* __restrict__ bfc1_1, const float* __restrict__ wfc2_1, const float* __restrict__ bfc2_1,
    const float* __restrict__ bih2, const float* __restrict__ bhh2,
    const float* __restrict__ bfc1_2, const float* __restrict__ wfc2_2, const float* __restrict__ bfc2_2,
    float* __restrict__ v1, float* __restrict__ v2,
    float* __restrict__ ho1, float* __restrict__ ho2,
    int ntiles)
{
    extern __shared__ __align__(16) unsigned char sm[];
    unsigned char* XHI = sm + SM_X;
    unsigned char* XLO = sm + SM_X + 16384;
    unsigned char* HHI = sm + SM_HHI;
    unsigned char* HLO = sm + SM_HLO;
    float* VP  = (float*)(sm + SM_X + 24576);
    float* BIH = (float*)(sm + SM_BIH);
    float* BHH = (float*)(sm + SM_BHH);
    float* B1  = (float*)(sm + SM_B1);
    float* W2  = (float*)(sm + SM_W2);

    const int tid  = threadIdx.x;
    const int wid  = tid >> 5;
    const int lane = tid & 31;
    const int g    = lane >> 2;
    const int tq   = lane & 3;

    const int ms  = wid & 3;
    const int nq  = wid >> 2;
    const int rbase = 32 * ms;
    const int nb0   = 16 * nq;

    // ldmatrix per-lane components
    const int rowa = (lane & 7) + 8 * ((lane >> 3) & 1);   // A frag row within 16-strip
    const int cca  = lane >> 4;                             // A granule sub (0,1)
    const int nB   = nb0 + ((lane >> 4) << 3) + (lane & 7); // B x4 row (both ng)
    const int binc = (lane >> 3) & 1;                       // B granule sub

    const uint32_t smb  = smem_u32(sm);
    const uint32_t Wu   = smb + SM_W;
    const uint32_t Xu   = smb + SM_X;
    const uint32_t XHIu = Xu;
    const uint32_t XLOu = Xu + 16384;
    const uint32_t HHIu = smb + SM_HHI;
    const uint32_t HLOu = smb + SM_HLO;

    const int stream = (blockIdx.x >= HCTA) ? 1 : 0;
    const int local  = blockIdx.x - HCTA * stream;

    const float* hin = stream ? h2 : h1;
    const float* bih = stream ? bih2 : bih1;
    const float* bhh = stream ? bhh2 : bhh1;
    const float* bf1 = stream ? bfc1_2 : bfc1_1;
    const float* wf2 = stream ? wfc2_2 : wfc2_1;
    const float* bf2 = stream ? bfc2_2 : bfc2_1;
    float* vout = stream ? v2 : v1;
    float* hout = stream ? ho2 : ho1;

    const int orow = tid >> 2;
    const int ogr  = tid & 3;
    const uint32_t obs_soff = (uint32_t)(orow * 64 + ((ogr ^ ((orow >> 1) & 3)) << 4));

    // ---- one-time: all 20 weight tiles + biases into smem ----
    {
        const int4* src = (const int4*)&g_wt[stream][0][0];
        int4* dst = (int4*)sm;
        for (int i = tid; i < (20 * TILE_B) / 16; i += NT) dst[i] = src[i];
    }
    for (int i = tid; i < 192; i += NT) { BIH[i] = bih[i]; BHH[i] = bhh[i]; }
    if (tid < 64) { B1[tid] = bf1[tid]; W2[tid] = wf2[tid]; }
    const float bias2 = bf2[0];
    __syncthreads();

    // ---- prologue: first tile H planes + obs chunk0 prefetch ----
    float4 pre0, pre1;
    {
        const int row0 = local * 128;
#pragma unroll
        for (int it = 0; it < 2; ++it) {
            int idx = tid + it * NT;
            int r = idx >> 3, gg = idx & 7;
            const float* p = hin + (size_t)(row0 + r) * 64 + gg * 8;
            float4 v0 = *(const float4*)p;
            float4 v1 = *(const float4*)(p + 4);
            uint4 hi, lo;
            split2f(v0.x, v0.y, hi.x, lo.x);
            split2f(v0.z, v0.w, hi.y, lo.y);
            split2f(v1.x, v1.y, hi.z, lo.z);
            split2f(v1.z, v1.w, hi.w, lo.w);
            uint32_t off = (uint32_t)(r * 128 + ((gg ^ (r & 7)) << 4));
            *(uint4*)(HHI + off) = hi;
            *(uint4*)(HLO + off) = lo;
        }
        const float* p = obs + (size_t)(row0 + orow) * 256 + ogr * 8;
        pre0 = *(const float4*)p;
        pre1 = *(const float4*)(p + 4);
    }

    for (int tile = local; tile < ntiles; tile += HCTA) {
        const int row0 = tile * 128;

        // ---- Phase B: fc1 GEMM, K=256 in 8 chunks of 32, double-buffered ----
        float acc1[2][2][4];
#pragma unroll
        for (int st = 0; st < 2; ++st)
#pragma unroll
            for (int ng = 0; ng < 2; ++ng)
#pragma unroll
                for (int e = 0; e < 4; ++e) acc1[st][ng][e] = 0.0f;

        for (int kc = 0; kc < 8; ++kc) {
            {
                uint4 hi, lo;
                split2f(pre0.x, pre0.y, hi.x, lo.x);
                split2f(pre0.z, pre0.w, hi.y, lo.y);
                split2f(pre1.x, pre1.y, hi.z, lo.z);
                split2f(pre1.z, pre1.w, hi.w, lo.w);
                unsigned char* bb = sm + SM_X + (kc & 1) * 16384;
                *(uint4*)(bb + obs_soff) = hi;
                *(uint4*)(bb + 8192 + obs_soff) = lo;
            }
            if (kc < 7) {
                const float* p = obs + (size_t)(row0 + orow) * 256 + (kc + 1) * 32 + ogr * 8;
                pre0 = *(const float4*)p;
                pre1 = *(const float4*)(p + 4);
            }
            __syncthreads();

            const uint32_t bufh = Xu + (uint32_t)((kc & 1) * 16384);
            const uint32_t bufl = bufh + 8192;
            const uint32_t bth = Wu + (uint32_t)(kc >> 1) * TILE_B;
            const uint32_t btl = bth + 4 * TILE_B;
#pragma unroll
            for (int ks = 0; ks < 2; ++ks) {
                uint32_t xh[2][4], xl[2][4];
#pragma unroll
                for (int st = 0; st < 2; ++st) {
                    int row = rbase + 16 * st + rowa;
                    uint32_t ro = (uint32_t)(row * 64 +
                                  (((ks * 2 + cca) ^ ((row >> 1) & 3)) << 4));
                    ldsm4(xh[st], bufh + ro);
                    ldsm4(xl[st], bufl + ro);
                }
                int gin = (kc & 1) * 4 + ks * 2 + binc;
                uint32_t no = (uint32_t)(nB * 128 + ((gin ^ (nB & 7)) << 4));
                uint32_t bh[4], bl[4];
                ldsm4(bh, bth + no);
                ldsm4(bl, btl + no);
#pragma unroll
                for (int ng = 0; ng < 2; ++ng) {
                    const uint32_t* bhp = &bh[ng * 2];
                    const uint32_t* blp = &bl[ng * 2];
                    mma16816(acc1[0][ng], xh[0], bhp);  mma16816(acc1[1][ng], xh[1], bhp);
                    mma16816(acc1[0][ng], xh[0], blp);  mma16816(acc1[1][ng], xh[1], blp);
                    mma16816(acc1[0][ng], xl[0], bhp);  mma16816(acc1[1][ng], xl[1], bhp);
                }
            }
        }
        __syncthreads();   // last chunk MMA done; X region reusable for X planes

        // ---- Phase C: X = tanh(acc+b) -> X planes ([128][128B], ^(r&7) swizzle) ----
#pragma unroll
        for (int st = 0; st < 2; ++st)
#pragma unroll
            for (int ng = 0; ng < 2; ++ng) {
                int col = nb0 + 8 * ng + 2 * tq;
                int ra = rbase + 16 * st + g;
                int rb = ra + 8;
                float x0 = ftanh(acc1[st][ng][0] + B1[col]);
                float x1 = ftanh(acc1[st][ng][1] + B1[col + 1]);
                float x2 = ftanh(acc1[st][ng][2] + B1[col]);
                float x3 = ftanh(acc1[st][ng][3] + B1[col + 1]);
                uint32_t hi01, lo01, hi23, lo23;
                split2f(x0, x1, hi01, lo01);
                split2f(x2, x3, hi23, lo23);
                uint32_t offa = (uint32_t)(ra * 128 + (((col >> 3) ^ (ra & 7)) << 4) + (col & 7) * 2);
                uint32_t offb = (uint32_t)(rb * 128 + (((col >> 3) ^ (rb & 7)) << 4) + (col & 7) * 2);
                *(uint32_t*)(XHI + offa) = hi01;  *(uint32_t*)(XLO + offa) = lo01;
                *(uint32_t*)(XHI + offb) = hi23;  *(uint32_t*)(XLO + offb) = lo23;
            }
        __syncthreads();

        // ---- Phase E pass 1: X-side gate GEMMs (slots 8..13) ----
        // per (ng,st): full 3-term split, 9 MMA groups:
        //   x_hi*w_hi, x_lo*w_hi, x_hi*w_lo for each of r, z, n
        float ar[2][2][4], az[2][2][4], ani[2][2][4];
#pragma unroll
        for (int st = 0; st < 2; ++st)
#pragma unroll
            for (int ng = 0; ng < 2; ++ng)
#pragma unroll
                for (int e = 0; e < 4; ++e) { ar[st][ng][e] = az[st][ng][e] = ani[st][ng][e] = 0.0f; }

#pragma unroll
        for (int ks = 0; ks < 4; ++ks) {
            uint32_t axh[2][4], axl[2][4];
#pragma unroll
            for (int st = 0; st < 2; ++st) {
                int row = rbase + 16 * st + rowa;
                uint32_t ro = (uint32_t)(row * 128 + (((ks * 2 + cca) ^ (row & 7)) << 4));
                ldsm4(axh[st], XHIu + ro);
                ldsm4(axl[st], XLOu + ro);
            }
            int gin = ks * 2 + binc;
            uint32_t no = (uint32_t)(nB * 128 + ((gin ^ (nB & 7)) << 4));
            uint32_t brh[4], bzh[4], bnh_[4], brl[4], bzl[4], bnl[4];
            ldsm4(brh,  Wu + 8  * TILE_B + no);
            ldsm4(bzh,  Wu + 9  * TILE_B + no);
            ldsm4(bnh_, Wu + 10 * TILE_B + no);
            ldsm4(brl,  Wu + 11 * TILE_B + no);
            ldsm4(bzl,  Wu + 12 * TILE_B + no);
            ldsm4(bnl,  Wu + 13 * TILE_B + no);
#pragma unroll
            for (int ng = 0; ng < 2; ++ng) {
#pragma unroll
                for (int st = 0; st < 2; ++st) {
                    mma16816(ar[st][ng],  axh[st], &brh[ng * 2]);
                    mma16816(az[st][ng],  axh[st], &bzh[ng * 2]);
                    mma16816(ani[st][ng], axh[st], &bnh_[ng * 2]);
                    mma16816(ar[st][ng],  axl[st], &brh[ng * 2]);
                    mma16816(az[st][ng],  axl[st], &bzh[ng * 2]);
                    mma16816(ani[st][ng], axl[st], &bnh_[ng * 2]);
                    mma16816(ar[st][ng],  axh[st], &brl[ng * 2]);
                    mma16816(az[st][ng],  axh[st], &bzl[ng * 2]);
                    mma16816(ani[st][ng], axh[st], &bnl[ng * 2]);
                }
            }
        }

        // ---- Phase E pass 2: H-side gate GEMMs (slots 14..19) ----
        float anh[2][2][4];
#pragma unroll
        for (int st = 0; st < 2; ++st)
#pragma unroll
            for (int ng = 0; ng < 2; ++ng)
#pragma unroll
                for (int e = 0; e < 4; ++e) anh[st][ng][e] = 0.0f;

#pragma unroll
        for (int ks = 0; ks < 4; ++ks) {
            uint32_t ahh[2][4], ahl[2][4];
#pragma unroll
            for (int st = 0; st < 2; ++st) {
                int row = rbase + 16 * st + rowa;
                uint32_t ro = (uint32_t)(row * 128 + (((ks * 2 + cca) ^ (row & 7)) << 4));
                ldsm4(ahh[st], HHIu + ro);
                ldsm4(ahl[st], HLOu + ro);
            }
            int gin = ks * 2 + binc;
            uint32_t no = (uint32_t)(nB * 128 + ((gin ^ (nB & 7)) << 4));
            uint32_t brh[4], bzh[4], bnh_[4], brl[4], bzl[4], bnl[4];
            ldsm4(brh,  Wu + 14 * TILE_B + no);
            ldsm4(bzh,  Wu + 15 * TILE_B + no);
            ldsm4(bnh_, Wu + 16 * TILE_B + no);
            ldsm4(brl,  Wu + 17 * TILE_B + no);
            ldsm4(bzl,  Wu + 18 * TILE_B + no);
            ldsm4(bnl,  Wu + 19 * TILE_B + no);
#pragma unroll
            for (int ng = 0; ng < 2; ++ng) {
#pragma unroll
                for (int st = 0; st < 2; ++st) {
                    mma16816(ar[st][ng],  ahh[st], &brh[ng * 2]);
                    mma16816(az[st][ng],  ahh[st], &bzh[ng * 2]);
                    mma16816(anh[st][ng], ahh[st], &bnh_[ng * 2]);
                    mma16816(ar[st][ng],  ahl[st], &brh[ng * 2]);
                    mma16816(az[st][ng],  ahl[st], &bzh[ng * 2]);
                    mma16816(anh[st][ng], ahl[st], &bnh_[ng * 2]);
                    mma16816(ar[st][ng],  ahh[st], &brl[ng * 2]);
                    mma16816(az[st][ng],  ahh[st], &bzl[ng * 2]);
                    mma16816(anh[st][ng], ahh[st], &bnl[ng * 2]);
                }
            }
        }
        __syncthreads();   // all X/H plane MMA reads done (VP overlay safe)

        // ---- epilogue: gates, mask, new_h direct STG, value partials ----
        float vp[4] = {0.0f, 0.0f, 0.0f, 0.0f};
#pragma unroll
        for (int st = 0; st < 2; ++st)
#pragma unroll
            for (int ng = 0; ng < 2; ++ng) {
                int cb = nb0 + 8 * ng + 2 * tq;
#pragma unroll
                for (int half = 0; half < 2; ++half) {
                    int row = rbase + 16 * st + g + 8 * half;
                    int m = mask[row0 + row];
                    uint32_t ho = (uint32_t)(row * 128 + (((cb >> 3) ^ (row & 7)) << 4) + (cb & 7) * 2);
                    uint32_t uh = *(const uint32_t*)(HHI + ho);
                    uint32_t ul = *(const uint32_t*)(HLO + ho);
                    float hold0 = __uint_as_float(uh << 16) + __uint_as_float(ul << 16);
                    float hold1 = __uint_as_float(uh & 0xffff0000u) + __uint_as_float(ul & 0xffff0000u);
                    float2 hv;
#pragma unroll
                    for (int e2 = 0; e2 < 2; ++e2) {
                        int e = 2 * half + e2;
                        int c = cb + e2;
                        float rr = fsigm(ar[st][ng][e] + BIH[c] + BHH[c]);
                        float zz = fsigm(az[st][ng][e] + BIH[64 + c] + BHH[64 + c]);
                        float nn = ftanh(ani[st][ng][e] + BIH[128 + c] +
                                         rr * (anh[st][ng][e] + BHH[128 + c]));
                        float hold = e2 ? hold1 : hold0;
                        float hg = (1.0f - zz) * nn + zz * hold;
                        float hn = m ? hg : hold;
                        if (e2) hv.y = hn; else hv.x = hn;
                        vp[st * 2 + half] += hn * W2[c];
                    }
                    *(float2*)(hout + (size_t)(row0 + row) * 64 + cb) = hv;
                }
            }

#pragma unroll
        for (int off = 1; off <= 2; off <<= 1)
#pragma unroll
            for (int q = 0; q < 4; ++q) vp[q] += __shfl_xor_sync(0xffffffffu, vp[q], off);
        if (tq == 0) {
#pragma unroll
            for (int st = 0; st < 2; ++st) {
                VP[(rbase + 16 * st + g) * 4 + nq]     = vp[st * 2];
                VP[(rbase + 16 * st + g + 8) * 4 + nq] = vp[st * 2 + 1];
            }
        }
        __syncthreads();

        if (tid < 128)
            vout[row0 + tid] = VP[tid * 4] + VP[tid * 4 + 1] + VP[tid * 4 + 2] + VP[tid * 4 + 3] + bias2;

        const int ntile = tile + HCTA;
        if (ntile < ntiles) {
            const int nrow0 = ntile * 128;
#pragma unroll
            for (int it = 0; it < 2; ++it) {
                int idx = tid + it * NT;
                int r = idx >> 3, gg = idx & 7;
                const float* p = hin + (size_t)(nrow0 + r) * 64 + gg * 8;
                float4 v0 = *(const float4*)p;
                float4 v1 = *(const float4*)(p + 4);
                uint4 hi, lo;
                split2f(v0.x, v0.y, hi.x, lo.x);
                split2f(v0.z, v0.w, hi.y, lo.y);
                split2f(v1.x, v1.y, hi.z, lo.z);
                split2f(v1.z, v1.w, hi.w, lo.w);
                uint32_t off = (uint32_t)(r * 128 + ((gg ^ (r & 7)) << 4));
                *(uint4*)(HHI + off) = hi;
                *(uint4*)(HLO + off) = lo;
            }
            const float* p = obs + (size_t)(nrow0 + orow) * 256 + ogr * 8;
            pre0 = *(const float4*)p;
            pre1 = *(const float4*)(p + 4);
        }
    }
}

// ---------------- launch ----------------
extern "C" void kernel_launch(void* const* d_in, const int* in_sizes, int n_in,
                              void* d_out, int out_size) {
    const float* obs = (const float*)d_in[0];
    const float* h1  = (const float*)d_in[1];
    const float* h2  = (const float*)d_in[2];
    const int*   msk = (const int*)d_in[3];

    const int B = in_sizes[1] / 64;   // 262144
    const int ntiles = B / 128;       // 2048

    float* out = (float*)d_out;
    float* v1  = out;
    float* v2  = out + (size_t)B;
    float* ho1 = out + 2 * (size_t)B;
    float* ho2 = ho1 + (size_t)B * 64;

    convert_weights_kernel<<<160, 256>>>(
        (const float*)d_in[4],  (const float*)d_in[6],  (const float*)d_in[7],
        (const float*)d_in[12], (const float*)d_in[14], (const float*)d_in[15]);

    cudaFuncSetAttribute(gru_hmma_kernel,
                         cudaFuncAttributeMaxDynamicSharedMemorySize, SMEM_TOTAL);

    gru_hmma_kernel<<<NCTA, NT, SMEM_TOTAL>>>(
        obs, h1, h2, msk,
        (const float*)d_in[8],  (const float*)d_in[9],
        (const float*)d_in[5],  (const float*)d_in[10], (const float*)d_in[11],
        (const float*)d_in[16], (const float*)d_in[17],
        (const float*)d_in[13], (const float*)d_in[18], (const float*)d_in[19],
        v1, v2, ho1, ho2, ntiles);
}

// round 11
// speedup vs baseline: 1.0006x; 1.0006x over previous
#include <cuda_runtime.h>
#include <cuda_bf16.h>
#include <stdint.h>

#define NT 512
#define NCTA 148
#define HCTA 74

// ---------------- math helpers ----------------
__device__ __forceinline__ float fsigm(float x) { return __fdividef(1.0f, 1.0f + __expf(-x)); }
__device__ __forceinline__ float ftanh(float x) {
    return 1.0f - __fdividef(2.0f, __expf(2.0f * x) + 1.0f);
}
__device__ __forceinline__ uint32_t cvt_bf16x2(float x, float y) {   // lo=x, hi=y
    uint32_t r;
    asm("cvt.rn.bf16x2.f32 %0, %1, %2;" : "=r"(r) : "f"(y), "f"(x));
    return r;
}
__device__ __forceinline__ void split2f(float a, float b, uint32_t& hi, uint32_t& lo) {
    hi = cvt_bf16x2(a, b);
    float af = __uint_as_float(hi << 16);
    float bf = __uint_as_float(hi & 0xffff0000u);
    lo = cvt_bf16x2(a - af, b - bf);
}
__device__ __forceinline__ uint32_t smem_u32(const void* p) {
    uint32_t a;
    asm("{ .reg .u64 t; cvta.to.shared.u64 t, %1; cvt.u32.u64 %0, t; }" : "=r"(a) : "l"(p));
    return a;
}

// ---------------- mma + ldmatrix ----------------
__device__ __forceinline__ void mma16816(float* c, const uint32_t* a, const uint32_t* b) {
    asm volatile(
        "mma.sync.aligned.m16n8k16.row.col.f32.bf16.bf16.f32 "
        "{%0,%1,%2,%3}, {%4,%5,%6,%7}, {%8,%9}, {%0,%1,%2,%3};"
        : "+f"(c[0]), "+f"(c[1]), "+f"(c[2]), "+f"(c[3])
        : "r"(a[0]), "r"(a[1]), "r"(a[2]), "r"(a[3]), "r"(b[0]), "r"(b[1]));
}
__device__ __forceinline__ void ldsm4(uint32_t* d, uint32_t addr) {
    asm volatile("ldmatrix.sync.aligned.m8n8.x4.shared.b16 {%0,%1,%2,%3}, [%4];"
                 : "=r"(d[0]), "=r"(d[1]), "=r"(d[2]), "=r"(d[3]) : "r"(addr));
}

// ---------------- weight scratch: swizzled [64][64] bf16 tiles, 8KB each ------
// half-index for (row n, col k): n*64 + ((k>>3 ^ (n&7))<<3) + (k&7)
#define TILE_B 8192
#define TILE_H 4096
__device__ __align__(16) __nv_bfloat16 g_wt[2][20][TILE_H];

__global__ void convert_weights_kernel(
    const float* __restrict__ fc1a, const float* __restrict__ wiha, const float* __restrict__ whha,
    const float* __restrict__ fc1b, const float* __restrict__ wihb, const float* __restrict__ whhb)
{
    int tid = blockIdx.x * blockDim.x + threadIdx.x;
    int stride = gridDim.x * blockDim.x;
    for (int s = 0; s < 2; ++s) {
        const float* fc1 = s ? fc1b : fc1a;
        const float* wih = s ? wihb : wiha;
        const float* whh = s ? whhb : whha;
        for (int e = tid; e < 40960; e += stride) {
            float v; int th, tl, n, k;
            if (e < 16384) {                        // fc1 [64,256] -> tiles 0..7
                n = e >> 8; int kf = e & 255; int kc = kf >> 6; k = kf & 63;
                v = fc1[e]; th = kc; tl = 4 + kc;
            } else if (e < 28672) {                 // wih [192,64] -> tiles 8..13
                int e2 = e - 16384, j = e2 >> 6; k = e2 & 63; int gg = j >> 6; n = j & 63;
                v = wih[e2]; th = 8 + gg; tl = 11 + gg;
            } else {                                // whh [192,64] -> tiles 14..19
                int e2 = e - 28672, j = e2 >> 6; k = e2 & 63; int gg = j >> 6; n = j & 63;
                v = whh[e2]; th = 14 + gg; tl = 17 + gg;
            }
            uint32_t off = n * 64 + (((k >> 3) ^ (n & 7)) << 3) + (k & 7);
            __nv_bfloat16 hi = __float2bfloat16(v);
            __nv_bfloat16 lo = __float2bfloat16(v - __bfloat162float(hi));
            g_wt[s][th][off] = hi;
            g_wt[s][tl][off] = lo;
        }
    }
}

// ---------------- smem layout (bytes) ----------------
#define SM_W    0                 // 20 tiles = 163840
#define SM_X    163840            // 32KB: Phase B ping-pong (2x16KB) / X planes / VP @+24K
#define SM_HHI  196608            // [128 rows][128 B]
#define SM_HLO  212992
#define SM_BIH  229376            // float[192]
#define SM_BHH  230144
#define SM_B1   230912
#define SM_W2   231168
#define SMEM_TOTAL 231424

__global__ __launch_bounds__(NT, 1)
void gru_hmma_kernel(
    const float* __restrict__ obs, const float* __restrict__ h1, const float* __restrict__ h2,
    const int* __restrict__ mask,
    const float* __restrict__ bih1, const float* __restrict__ bhh1,
    const float* __restrict__ bfc1_1, const float* __restrict__ wfc2_1, const float* __restrict__ bfc2_1,
    const float* __restrict__ bih2, const float* __restrict__ bhh2,
    const float* __restrict__ bfc1_2, const float* __restrict__ wfc2_2, const float* __restrict__ bfc2_2,
    float* __restrict__ v1, float* __restrict__ v2,
    float* __restrict__ ho1, float* __restrict__ ho2,
    int ntiles)
{
    extern __shared__ __align__(16) unsigned char sm[];
    unsigned char* XHI = sm + SM_X;
    unsigned char* XLO = sm + SM_X + 16384;
    unsigned char* HHI = sm + SM_HHI;
    unsigned char* HLO = sm + SM_HLO;
    float* VP  = (float*)(sm + SM_X + 24576);
    float* BIH = (float*)(sm + SM_BIH);
    float* BHH = (float*)(sm + SM_BHH);
    float* B1  = (float*)(sm + SM_B1);
    float* W2  = (float*)(sm + SM_W2);

    const int tid  = threadIdx.x;
    const int wid  = tid >> 5;
    const int lane = tid & 31;
    const int g    = lane >> 2;
    const int tq   = lane & 3;

    const int ms  = wid & 3;
    const int nq  = wid >> 2;
    const int rbase = 32 * ms;
    const int nb0   = 16 * nq;

    // ldmatrix per-lane components
    const int rowa = (lane & 7) + 8 * ((lane >> 3) & 1);   // A frag row within 16-strip
    const int cca  = lane >> 4;                             // A granule sub (0,1)
    const int nB   = nb0 + ((lane >> 4) << 3) + (lane & 7); // B x4 row (both ng)
    const int binc = (lane >> 3) & 1;                       // B granule sub

    const uint32_t smb  = smem_u32(sm);
    const uint32_t Wu   = smb + SM_W;
    const uint32_t Xu   = smb + SM_X;
    const uint32_t XHIu = Xu;
    const uint32_t XLOu = Xu + 16384;
    const uint32_t HHIu = smb + SM_HHI;
    const uint32_t HLOu = smb + SM_HLO;

    const int stream = (blockIdx.x >= HCTA) ? 1 : 0;
    const int local  = blockIdx.x - HCTA * stream;

    const float* hin = stream ? h2 : h1;
    const float* bih = stream ? bih2 : bih1;
    const float* bhh = stream ? bhh2 : bhh1;
    const float* bf1 = stream ? bfc1_2 : bfc1_1;
    const float* wf2 = stream ? wfc2_2 : wfc2_1;
    const float* bf2 = stream ? bfc2_2 : bfc2_1;
    float* vout = stream ? v2 : v1;
    float* hout = stream ? ho2 : ho1;

    const int orow = tid >> 2;
    const int ogr  = tid & 3;
    const uint32_t obs_soff = (uint32_t)(orow * 64 + ((ogr ^ ((orow >> 1) & 3)) << 4));

    // ---- one-time: all 20 weight tiles + biases into smem ----
    {
        const int4* src = (const int4*)&g_wt[stream][0][0];
        int4* dst = (int4*)sm;
        for (int i = tid; i < (20 * TILE_B) / 16; i += NT) dst[i] = src[i];
    }
    for (int i = tid; i < 192; i += NT) { BIH[i] = bih[i]; BHH[i] = bhh[i]; }
    if (tid < 64) { B1[tid] = bf1[tid]; W2[tid] = wf2[tid]; }
    const float bias2 = bf2[0];
    __syncthreads();

    // ---- prologue: first tile H planes + obs chunk0 prefetch ----
    float4 pre0, pre1;
    {
        const int row0 = local * 128;
#pragma unroll
        for (int it = 0; it < 2; ++it) {
            int idx = tid + it * NT;
            int r = idx >> 3, gg = idx & 7;
            const float* p = hin + (size_t)(row0 + r) * 64 + gg * 8;
            float4 v0 = *(const float4*)p;
            float4 v1 = *(const float4*)(p + 4);
            uint4 hi, lo;
            split2f(v0.x, v0.y, hi.x, lo.x);
            split2f(v0.z, v0.w, hi.y, lo.y);
            split2f(v1.x, v1.y, hi.z, lo.z);
            split2f(v1.z, v1.w, hi.w, lo.w);
            uint32_t off = (uint32_t)(r * 128 + ((gg ^ (r & 7)) << 4));
            *(uint4*)(HHI + off) = hi;
            *(uint4*)(HLO + off) = lo;
        }
        const float* p = obs + (size_t)(row0 + orow) * 256 + ogr * 8;
        pre0 = *(const float4*)p;
        pre1 = *(const float4*)(p + 4);
    }

    for (int tile = local; tile < ntiles; tile += HCTA) {
        const int row0 = tile * 128;

        // ---- Phase B: fc1 GEMM, K=256 in 8 chunks of 32, double-buffered ----
        float acc1[2][2][4];
#pragma unroll
        for (int st = 0; st < 2; ++st)
#pragma unroll
            for (int ng = 0; ng < 2; ++ng)
#pragma unroll
                for (int e = 0; e < 4; ++e) acc1[st][ng][e] = 0.0f;

        for (int kc = 0; kc < 8; ++kc) {
            {
                uint4 hi, lo;
                split2f(pre0.x, pre0.y, hi.x, lo.x);
                split2f(pre0.z, pre0.w, hi.y, lo.y);
                split2f(pre1.x, pre1.y, hi.z, lo.z);
                split2f(pre1.z, pre1.w, hi.w, lo.w);
                unsigned char* bb = sm + SM_X + (kc & 1) * 16384;
                *(uint4*)(bb + obs_soff) = hi;
                *(uint4*)(bb + 8192 + obs_soff) = lo;
            }
            if (kc < 7) {
                const float* p = obs + (size_t)(row0 + orow) * 256 + (kc + 1) * 32 + ogr * 8;
                pre0 = *(const float4*)p;
                pre1 = *(const float4*)(p + 4);
            }
            __syncthreads();

            const uint32_t bufh = Xu + (uint32_t)((kc & 1) * 16384);
            const uint32_t bufl = bufh + 8192;
            const uint32_t bth = Wu + (uint32_t)(kc >> 1) * TILE_B;
            const uint32_t btl = bth + 4 * TILE_B;
#pragma unroll
            for (int ks = 0; ks < 2; ++ks) {
                uint32_t xh[2][4], xl[2][4], bh[4], bl[4];
#pragma unroll
                for (int st = 0; st < 2; ++st) {
                    int row = rbase + 16 * st + rowa;
                    uint32_t ro = (uint32_t)(row * 64 +
                                  (((ks * 2 + cca) ^ ((row >> 1) & 3)) << 4));
                    ldsm4(xh[st], bufh + ro);
                    ldsm4(xl[st], bufl + ro);
                }
                int gin = (kc & 1) * 4 + ks * 2 + binc;
                uint32_t no = (uint32_t)(nB * 128 + ((gin ^ (nB & 7)) << 4));
                ldsm4(bh, bth + no);
                ldsm4(bl, btl + no);
                // spacing-4 emission: term-major, (ng,st) inner
                mma16816(acc1[0][0], xh[0], &bh[0]);  mma16816(acc1[1][0], xh[1], &bh[0]);
                mma16816(acc1[0][1], xh[0], &bh[2]);  mma16816(acc1[1][1], xh[1], &bh[2]);
                mma16816(acc1[0][0], xh[0], &bl[0]);  mma16816(acc1[1][0], xh[1], &bl[0]);
                mma16816(acc1[0][1], xh[0], &bl[2]);  mma16816(acc1[1][1], xh[1], &bl[2]);
                mma16816(acc1[0][0], xl[0], &bh[0]);  mma16816(acc1[1][0], xl[1], &bh[0]);
                mma16816(acc1[0][1], xl[0], &bh[2]);  mma16816(acc1[1][1], xl[1], &bh[2]);
            }
        }
        __syncthreads();   // last chunk MMA done; X region reusable for X planes

        // ---- Phase C (X plane writes) fused with Pass 2 (H-side gate GEMMs) ----
        // C writes X+0..32K; pass2 reads H planes + slots 14..19 — disjoint.
#pragma unroll
        for (int st = 0; st < 2; ++st)
#pragma unroll
            for (int ng = 0; ng < 2; ++ng) {
                int col = nb0 + 8 * ng + 2 * tq;
                int ra = rbase + 16 * st + g;
                int rb = ra + 8;
                float x0 = ftanh(acc1[st][ng][0] + B1[col]);
                float x1 = ftanh(acc1[st][ng][1] + B1[col + 1]);
                float x2 = ftanh(acc1[st][ng][2] + B1[col]);
                float x3 = ftanh(acc1[st][ng][3] + B1[col + 1]);
                uint32_t hi01, lo01, hi23, lo23;
                split2f(x0, x1, hi01, lo01);
                split2f(x2, x3, hi23, lo23);
                uint32_t offa = (uint32_t)(ra * 128 + (((col >> 3) ^ (ra & 7)) << 4) + (col & 7) * 2);
                uint32_t offb = (uint32_t)(rb * 128 + (((col >> 3) ^ (rb & 7)) << 4) + (col & 7) * 2);
                *(uint32_t*)(XHI + offa) = hi01;  *(uint32_t*)(XLO + offa) = lo01;
                *(uint32_t*)(XHI + offb) = hi23;  *(uint32_t*)(XLO + offb) = lo23;
            }

        float ar[2][2][4], az[2][2][4], anh[2][2][4];
#pragma unroll
        for (int st = 0; st < 2; ++st)
#pragma unroll
            for (int ng = 0; ng < 2; ++ng)
#pragma unroll
                for (int e = 0; e < 4; ++e) { ar[st][ng][e] = az[st][ng][e] = anh[st][ng][e] = 0.0f; }

#pragma unroll
        for (int ks = 0; ks < 4; ++ks) {
            uint32_t ahh[2][4], ahl[2][4];
#pragma unroll
            for (int st = 0; st < 2; ++st) {
                int row = rbase + 16 * st + rowa;
                uint32_t ro = (uint32_t)(row * 128 + (((ks * 2 + cca) ^ (row & 7)) << 4));
                ldsm4(ahh[st], HHIu + ro);
                ldsm4(ahl[st], HLOu + ro);
            }
            int gin = ks * 2 + binc;
            uint32_t no = (uint32_t)(nB * 128 + ((gin ^ (nB & 7)) << 4));
            uint32_t brh[4], bzh[4], bnh_[4], brl[4], bzl[4], bnl[4];
            ldsm4(brh,  Wu + 14 * TILE_B + no);
            ldsm4(bzh,  Wu + 15 * TILE_B + no);
            ldsm4(bnh_, Wu + 16 * TILE_B + no);
            ldsm4(brl,  Wu + 17 * TILE_B + no);
            ldsm4(bzl,  Wu + 18 * TILE_B + no);
            ldsm4(bnl,  Wu + 19 * TILE_B + no);
#pragma unroll
            for (int ng = 0; ng < 2; ++ng) {
                // spacing-6 emission: term-major, gate cycled, st inner
                mma16816(ar[0][ng],  ahh[0], &brh[ng * 2]);  mma16816(ar[1][ng],  ahh[1], &brh[ng * 2]);
                mma16816(az[0][ng],  ahh[0], &bzh[ng * 2]);  mma16816(az[1][ng],  ahh[1], &bzh[ng * 2]);
                mma16816(anh[0][ng], ahh[0], &bnh_[ng * 2]); mma16816(anh[1][ng], ahh[1], &bnh_[ng * 2]);
                mma16816(ar[0][ng],  ahl[0], &brh[ng * 2]);  mma16816(ar[1][ng],  ahl[1], &brh[ng * 2]);
                mma16816(az[0][ng],  ahl[0], &bzh[ng * 2]);  mma16816(az[1][ng],  ahl[1], &bzh[ng * 2]);
                mma16816(anh[0][ng], ahl[0], &bnh_[ng * 2]); mma16816(anh[1][ng], ahl[1], &bnh_[ng * 2]);
                mma16816(ar[0][ng],  ahh[0], &brl[ng * 2]);  mma16816(ar[1][ng],  ahh[1], &brl[ng * 2]);
                mma16816(az[0][ng],  ahh[0], &bzl[ng * 2]);  mma16816(az[1][ng],  ahh[1], &bzl[ng * 2]);
                mma16816(anh[0][ng], ahh[0], &bnl[ng * 2]);  mma16816(anh[1][ng], ahh[1], &bnl[ng * 2]);
            }
        }
        __syncthreads();   // X-plane writes visible; pass2 H reads done

        // ---- Pass 1: X-side gate GEMMs (slots 8..13) ----
        float ani[2][2][4];
#pragma unroll
        for (int st = 0; st < 2; ++st)
#pragma unroll
            for (int ng = 0; ng < 2; ++ng)
#pragma unroll
                for (int e = 0; e < 4; ++e) ani[st][ng][e] = 0.0f;

#pragma unroll
        for (int ks = 0; ks < 4; ++ks) {
            uint32_t axh[2][4], axl[2][4];
#pragma unroll
            for (int st = 0; st < 2; ++st) {
                int row = rbase + 16 * st + rowa;
                uint32_t ro = (uint32_t)(row * 128 + (((ks * 2 + cca) ^ (row & 7)) << 4));
                ldsm4(axh[st], XHIu + ro);
                ldsm4(axl[st], XLOu + ro);
            }
            int gin = ks * 2 + binc;
            uint32_t no = (uint32_t)(nB * 128 + ((gin ^ (nB & 7)) << 4));
            uint32_t brh[4], bzh[4], bnh_[4], brl[4], bzl[4], bnl[4];
            ldsm4(brh,  Wu + 8  * TILE_B + no);
            ldsm4(bzh,  Wu + 9  * TILE_B + no);
            ldsm4(bnh_, Wu + 10 * TILE_B + no);
            ldsm4(brl,  Wu + 11 * TILE_B + no);
            ldsm4(bzl,  Wu + 12 * TILE_B + no);
            ldsm4(bnl,  Wu + 13 * TILE_B + no);
#pragma unroll
            for (int ng = 0; ng < 2; ++ng) {
                mma16816(ar[0][ng],  axh[0], &brh[ng * 2]);  mma16816(ar[1][ng],  axh[1], &brh[ng * 2]);
                mma16816(az[0][ng],  axh[0], &bzh[ng * 2]);  mma16816(az[1][ng],  axh[1], &bzh[ng * 2]);
                mma16816(ani[0][ng], axh[0], &bnh_[ng * 2]); mma16816(ani[1][ng], axh[1], &bnh_[ng * 2]);
                mma16816(ar[0][ng],  axl[0], &brh[ng * 2]);  mma16816(ar[1][ng],  axl[1], &brh[ng * 2]);
                mma16816(az[0][ng],  axl[0], &bzh[ng * 2]);  mma16816(az[1][ng],  axl[1], &bzh[ng * 2]);
                mma16816(ani[0][ng], axl[0], &bnh_[ng * 2]); mma16816(ani[1][ng], axl[1], &bnh_[ng * 2]);
                mma16816(ar[0][ng],  axh[0], &brl[ng * 2]);  mma16816(ar[1][ng],  axh[1], &brl[ng * 2]);
                mma16816(az[0][ng],  axh[0], &bzl[ng * 2]);  mma16816(az[1][ng],  axh[1], &bzl[ng * 2]);
                mma16816(ani[0][ng], axh[0], &bnl[ng * 2]);  mma16816(ani[1][ng], axh[1], &bnl[ng * 2]);
            }
        }
        __syncthreads();   // all X/H plane reads done (VP overlay + H-plane reuse safe)

        // ---- fused interval: epilogue(t) ∥ phaseA(t+1) ∥ obs prefetch(t+1) ----
        const int  ntile = tile + HCTA;
        const bool have_next = (ntile < ntiles);
        const int  nrow0 = ntile * 128;

        // fire next-tile loads first (latency overlapped with epilogue math)
        float4 nh[2][2];
        if (have_next) {
#pragma unroll
            for (int it = 0; it < 2; ++it) {
                int idx = tid + it * NT;
                int r = idx >> 3, gg = idx & 7;
                const float* p = hin + (size_t)(nrow0 + r) * 64 + gg * 8;
                nh[it][0] = *(const float4*)p;
                nh[it][1] = *(const float4*)(p + 4);
            }
            const float* p = obs + (size_t)(nrow0 + orow) * 256 + ogr * 8;
            pre0 = *(const float4*)p;
            pre1 = *(const float4*)(p + 4);
        }

        // batch hold + mask loads (gmem, L2-hot)
        float2 hold[2][2][2];   // [st][ng][half]
        int mk[4];              // [st*2+half]
#pragma unroll
        for (int st = 0; st < 2; ++st) {
            mk[st * 2]     = mask[row0 + rbase + 16 * st + g];
            mk[st * 2 + 1] = mask[row0 + rbase + 16 * st + g + 8];
#pragma unroll
            for (int ng = 0; ng < 2; ++ng) {
                int cb = nb0 + 8 * ng + 2 * tq;
#pragma unroll
                for (int half = 0; half < 2; ++half) {
                    int row = rbase + 16 * st + g + 8 * half;
                    hold[st][ng][half] = *(const float2*)(hin + (size_t)(row0 + row) * 64 + cb);
                }
            }
        }

        float vp[4] = {0.0f, 0.0f, 0.0f, 0.0f};
#pragma unroll
        for (int st = 0; st < 2; ++st)
#pragma unroll
            for (int ng = 0; ng < 2; ++ng) {
                int cb = nb0 + 8 * ng + 2 * tq;
#pragma unroll
                for (int half = 0; half < 2; ++half) {
                    int row = rbase + 16 * st + g + 8 * half;
                    int m = mk[st * 2 + half];
                    float2 hv;
#pragma unroll
                    for (int e2 = 0; e2 < 2; ++e2) {
                        int e = 2 * half + e2;
                        int c = cb + e2;
                        float rr = fsigm(ar[st][ng][e] + BIH[c] + BHH[c]);
                        float zz = fsigm(az[st][ng][e] + BIH[64 + c] + BHH[64 + c]);
                        float nn = ftanh(ani[st][ng][e] + BIH[128 + c] +
                                         rr * (anh[st][ng][e] + BHH[128 + c]));
                        float ho = e2 ? hold[st][ng][half].y : hold[st][ng][half].x;
                        float hg = (1.0f - zz) * nn + zz * ho;
                        float hn = m ? hg : ho;
                        if (e2) hv.y = hn; else hv.x = hn;
                        vp[st * 2 + half] += hn * W2[c];
                    }
                    *(float2*)(hout + (size_t)(row0 + row) * 64 + cb) = hv;
                }
            }

#pragma unroll
        for (int off = 1; off <= 2; off <<= 1)
#pragma unroll
            for (int q = 0; q < 4; ++q) vp[q] += __shfl_xor_sync(0xffffffffu, vp[q], off);
        if (tq == 0) {
#pragma unroll
            for (int st = 0; st < 2; ++st) {
                VP[(rbase + 16 * st + g) * 4 + nq]     = vp[st * 2];
                VP[(rbase + 16 * st + g + 8) * 4 + nq] = vp[st * 2 + 1];
            }
        }

        // phase A(t+1): convert + store H planes (H planes free since pass2)
        if (have_next) {
#pragma unroll
            for (int it = 0; it < 2; ++it) {
                int idx = tid + it * NT;
                int r = idx >> 3, gg = idx & 7;
                uint4 hi, lo;
                split2f(nh[it][0].x, nh[it][0].y, hi.x, lo.x);
                split2f(nh[it][0].z, nh[it][0].w, hi.y, lo.y);
                split2f(nh[it][1].x, nh[it][1].y, hi.z, lo.z);
                split2f(nh[it][1].z, nh[it][1].w, hi.w, lo.w);
                uint32_t off = (uint32_t)(r * 128 + ((gg ^ (r & 7)) << 4));
                *(uint4*)(HHI + off) = hi;
                *(uint4*)(HLO + off) = lo;
            }
        }
        __syncthreads();   // VP visible; H planes(t+1) ready

        if (tid < 128)
            vout[row0 + tid] = VP[tid * 4] + VP[tid * 4 + 1] + VP[tid * 4 + 2] + VP[tid * 4 + 3] + bias2;
    }
}

// ---------------- launch ----------------
extern "C" void kernel_launch(void* const* d_in, const int* in_sizes, int n_in,
                              void* d_out, int out_size) {
    const float* obs = (const float*)d_in[0];
    const float* h1  = (const float*)d_in[1];
    const float* h2  = (const float*)d_in[2];
    const int*   msk = (const int*)d_in[3];

    const int B = in_sizes[1] / 64;   // 262144
    const int ntiles = B / 128;       // 2048

    float* out = (float*)d_out;
    float* v1  = out;
    float* v2  = out + (size_t)B;
    float* ho1 = out + 2 * (size_t)B;
    float* ho2 = ho1 + (size_t)B * 64;

    convert_weights_kernel<<<160, 256>>>(
        (const float*)d_in[4],  (const float*)d_in[6],  (const float*)d_in[7],
        (const float*)d_in[12], (const float*)d_in[14], (const float*)d_in[15]);

    cudaFuncSetAttribute(gru_hmma_kernel,
                         cudaFuncAttributeMaxDynamicSharedMemorySize, SMEM_TOTAL);

    gru_hmma_kernel<<<NCTA, NT, SMEM_TOTAL>>>(
        obs, h1, h2, msk,
        (const float*)d_in[8],  (const float*)d_in[9],
        (const float*)d_in[5],  (const float*)d_in[10], (const float*)d_in[11],
        (const float*)d_in[16], (const float*)d_in[17],
        (const float*)d_in[13], (const float*)d_in[18], (const float*)d_in[19],
        v1, v2, ho1, ho2, ntiles);
}

// round 13
// speedup vs baseline: 1.1604x; 1.1597x over previous
#include <cuda_runtime.h>
#include <cuda_fp16.h>
#include <stdint.h>

#define NT 512
#define NCTA 148
#define HCTA 74

// ---------------- math helpers ----------------
__device__ __forceinline__ float fsigm(float x) { return __fdividef(1.0f, 1.0f + __expf(-x)); }
__device__ __forceinline__ float ftanh(float x) {
    return 1.0f - __fdividef(2.0f, __expf(2.0f * x) + 1.0f);
}
__device__ __forceinline__ uint32_t h2u(float a, float b) {   // lo=a, hi=b
    __half2 h = __floats2half2_rn(a, b);
    return *(uint32_t*)&h;
}
__device__ __forceinline__ uint32_t smem_u32(const void* p) {
    uint32_t a;
    asm("{ .reg .u64 t; cvta.to.shared.u64 t, %1; cvt.u32.u64 %0, t; }" : "=r"(a) : "l"(p));
    return a;
}

// ---------------- mma (fp16 in, fp32 acc) + ldmatrix ----------------
__device__ __forceinline__ void mma16816(float* c, const uint32_t* a, const uint32_t* b) {
    asm volatile(
        "mma.sync.aligned.m16n8k16.row.col.f32.f16.f16.f32 "
        "{%0,%1,%2,%3}, {%4,%5,%6,%7}, {%8,%9}, {%0,%1,%2,%3};"
        : "+f"(c[0]), "+f"(c[1]), "+f"(c[2]), "+f"(c[3])
        : "r"(a[0]), "r"(a[1]), "r"(a[2]), "r"(a[3]), "r"(b[0]), "r"(b[1]));
}
__device__ __forceinline__ void ldsm4(uint32_t* d, uint32_t addr) {
    asm volatile("ldmatrix.sync.aligned.m8n8.x4.shared.b16 {%0,%1,%2,%3}, [%4];"
                 : "=r"(d[0]), "=r"(d[1]), "=r"(d[2]), "=r"(d[3]) : "r"(addr));
}

// ---------------- weight scratch: swizzled [64][64] fp16 tiles, 8KB each ------
// half-index for (row n, col k): n*64 + ((k>>3 ^ (n&7))<<3) + (k&7)
// tiles: 0-3 fc1_hi(kc) 4-7 fc1_lo(kc)
//        8=ih_r_hi 9=ih_z_hi 10=ih_n_hi 11=ih_r_lo 12=ih_z_lo 13=ih_n_lo
//       14=hh_r_hi 15=hh_z_hi 16=hh_n_hi 17=hh_r_lo 18=hh_z_lo 19=hh_n_lo
#define TILE_B 8192
#define TILE_H 4096
__device__ __align__(16) __half g_wt[2][20][TILE_H];

__global__ void convert_weights_kernel(
    const float* __restrict__ fc1a, const float* __restrict__ wiha, const float* __restrict__ whha,
    const float* __restrict__ fc1b, const float* __restrict__ wihb, const float* __restrict__ whhb)
{
    int tid = blockIdx.x * blockDim.x + threadIdx.x;
    int stride = gridDim.x * blockDim.x;
    for (int s = 0; s < 2; ++s) {
        const float* fc1 = s ? fc1b : fc1a;
        const float* wih = s ? wihb : wiha;
        const float* whh = s ? whhb : whha;
        for (int e = tid; e < 40960; e += stride) {
            float v; int th, tl, n, k;
            if (e < 16384) {                        // fc1 [64,256] -> tiles 0..7
                n = e >> 8; int kf = e & 255; int kc = kf >> 6; k = kf & 63;
                v = fc1[e]; th = kc; tl = 4 + kc;
            } else if (e < 28672) {                 // wih [192,64] -> tiles 8..13
                int e2 = e - 16384, j = e2 >> 6; k = e2 & 63; int gg = j >> 6; n = j & 63;
                v = wih[e2]; th = 8 + gg; tl = 11 + gg;
            } else {                                // whh [192,64] -> tiles 14..19
                int e2 = e - 28672, j = e2 >> 6; k = e2 & 63; int gg = j >> 6; n = j & 63;
                v = whh[e2]; th = 14 + gg; tl = 17 + gg;
            }
            uint32_t off = n * 64 + (((k >> 3) ^ (n & 7)) << 3) + (k & 7);
            __half hi = __float2half_rn(v);
            __half lo = __float2half_rn(v - __half2float(hi));
            g_wt[s][th][off] = hi;
            g_wt[s][tl][off] = lo;
        }
    }
}

// ---------------- smem layout (bytes) ----------------
#define SM_W    0                 // 20 tiles = 163840
#define SM_X    163840            // Phase B: buf0 @+0 (8KB), buf1 @+8192 (8KB)
                                  // Phase C/E: X plane @+0 (16KB); VP @+24576
#define SM_H    196608            // H plane [128 rows][128 B] = 16KB
#define SM_BIH  212992            // float[192]
#define SM_BHH  213760            // float[192]
#define SM_B1   214528            // float[64]
#define SM_W2   214784            // float[64]
#define SMEM_TOTAL 215040

__global__ __launch_bounds__(NT, 1)
void gru_hmma_kernel(
    const float* __restrict__ obs, const float* __restrict__ h1, const float* __restrict__ h2,
    const int* __restrict__ mask,
    const float* __restrict__ bih1, const float* __restrict__ bhh1,
    const float* __restrict__ bfc1_1, const float* __restrict__ wfc2_1, const float* __restrict__ bfc2_1,
    const float* __restrict__ bih2, const float* __restrict__ bhh2,
    const float* __restrict__ bfc1_2, const float* __restrict__ wfc2_2, const float* __restrict__ bfc2_2,
    float* __restrict__ v1, float* __restrict__ v2,
    float* __restrict__ ho1, float* __restrict__ ho2,
    int ntiles)
{
    extern __shared__ __align__(16) unsigned char sm[];
    unsigned char* XP = sm + SM_X;          // X plane (post-B)
    unsigned char* HP = sm + SM_H;          // H plane
    float* VP  = (float*)(sm + SM_X + 24576);
    float* BIH = (float*)(sm + SM_BIH);
    float* BHH = (float*)(sm + SM_BHH);
    float* B1  = (float*)(sm + SM_B1);
    float* W2  = (float*)(sm + SM_W2);

    const int tid  = threadIdx.x;
    const int lane = tid & 31;
    const int wid  = tid >> 5;
    const int g    = lane >> 2;
    const int tq   = lane & 3;

    const int ms  = wid & 3;
    const int nq  = wid >> 2;
    const int rbase = 32 * ms;
    const int nb0   = 16 * nq;

    // ldmatrix per-lane components
    const int rowa = (lane & 7) + 8 * ((lane >> 3) & 1);   // A frag row within 16-strip
    const int cca  = lane >> 4;                             // A granule sub (0,1)
    const int nB   = nb0 + ((lane >> 4) << 3) + (lane & 7); // B x4 row (both ng)
    const int binc = (lane >> 3) & 1;                       // B granule sub

    const uint32_t smb = smem_u32(sm);
    const uint32_t Wu  = smb + SM_W;
    const uint32_t Xu  = smb + SM_X;
    const uint32_t Hu  = smb + SM_H;

    const int stream = (blockIdx.x >= HCTA) ? 1 : 0;
    const int local  = blockIdx.x - HCTA * stream;

    const float* hin = stream ? h2 : h1;
    const float* bih = stream ? bih2 : bih1;
    const float* bhh = stream ? bhh2 : bhh1;
    const float* bf1 = stream ? bfc1_2 : bfc1_1;
    const float* wf2 = stream ? wfc2_2 : wfc2_1;
    const float* bf2 = stream ? bfc2_2 : bfc2_1;
    float* vout = stream ? v2 : v1;
    float* hout = stream ? ho2 : ho1;

    // obs-conversion task: thread owns (row orow, granule ogr) of each 32-col chunk
    const int orow = tid >> 2;
    const int ogr  = tid & 3;
    const uint32_t obs_soff = (uint32_t)(orow * 64 + ((ogr ^ ((orow >> 1) & 3)) << 4));

    // ---- one-time: all 20 weight tiles + biases into smem ----
    {
        const int4* src = (const int4*)&g_wt[stream][0][0];
        int4* dst = (int4*)sm;
        for (int i = tid; i < (20 * TILE_B) / 16; i += NT) dst[i] = src[i];
    }
    for (int i = tid; i < 192; i += NT) { BIH[i] = bih[i]; BHH[i] = bhh[i]; }
    if (tid < 64) { B1[tid] = bf1[tid]; W2[tid] = wf2[tid]; }
    const float bias2 = bf2[0];
    __syncthreads();

    // ---- prologue: first tile H plane + obs chunk0 prefetch ----
    float4 pre0, pre1;
    {
        const int row0 = local * 128;
#pragma unroll
        for (int it = 0; it < 2; ++it) {
            int idx = tid + it * NT;
            int r = idx >> 3, gg = idx & 7;
            const float* p = hin + (size_t)(row0 + r) * 64 + gg * 8;
            float4 v0 = *(const float4*)p;
            float4 v1 = *(const float4*)(p + 4);
            uint4 u;
            u.x = h2u(v0.x, v0.y);  u.y = h2u(v0.z, v0.w);
            u.z = h2u(v1.x, v1.y);  u.w = h2u(v1.z, v1.w);
            uint32_t off = (uint32_t)(r * 128 + ((gg ^ (r & 7)) << 4));
            *(uint4*)(HP + off) = u;
        }
        const float* p = obs + (size_t)(row0 + orow) * 256 + ogr * 8;
        pre0 = *(const float4*)p;
        pre1 = *(const float4*)(p + 4);
    }

    for (int tile = local; tile < ntiles; tile += HCTA) {
        const int row0 = tile * 128;

        // ---- Phase B: fc1 GEMM, K=256 in 8 chunks of 32, double-buffered ----
        float acc1[2][2][4];
#pragma unroll
        for (int st = 0; st < 2; ++st)
#pragma unroll
            for (int ng = 0; ng < 2; ++ng)
#pragma unroll
                for (int e = 0; e < 4; ++e) acc1[st][ng][e] = 0.0f;

        for (int kc = 0; kc < 8; ++kc) {
            {
                uint4 u;
                u.x = h2u(pre0.x, pre0.y);  u.y = h2u(pre0.z, pre0.w);
                u.z = h2u(pre1.x, pre1.y);  u.w = h2u(pre1.z, pre1.w);
                *(uint4*)(sm + SM_X + (kc & 1) * 8192 + obs_soff) = u;
            }
            if (kc < 7) {
                const float* p = obs + (size_t)(row0 + orow) * 256 + (kc + 1) * 32 + ogr * 8;
                pre0 = *(const float4*)p;
                pre1 = *(const float4*)(p + 4);
            }
            __syncthreads();

            const uint32_t buf = Xu + (uint32_t)((kc & 1) * 8192);
            const uint32_t bth = Wu + (uint32_t)(kc >> 1) * TILE_B;
            const uint32_t btl = bth + 4 * TILE_B;
#pragma unroll
            for (int ks = 0; ks < 2; ++ks) {
                uint32_t a[2][4], bh[4], bl[4];
#pragma unroll
                for (int st = 0; st < 2; ++st) {
                    int row = rbase + 16 * st + rowa;
                    uint32_t ro = (uint32_t)(row * 64 +
                                  (((ks * 2 + cca) ^ ((row >> 1) & 3)) << 4));
                    ldsm4(a[st], buf + ro);
                }
                int gin = (kc & 1) * 4 + ks * 2 + binc;
                uint32_t no = (uint32_t)(nB * 128 + ((gin ^ (nB & 7)) << 4));
                ldsm4(bh, bth + no);
                ldsm4(bl, btl + no);
                mma16816(acc1[0][0], a[0], &bh[0]);  mma16816(acc1[1][0], a[1], &bh[0]);
                mma16816(acc1[0][1], a[0], &bh[2]);  mma16816(acc1[1][1], a[1], &bh[2]);
                mma16816(acc1[0][0], a[0], &bl[0]);  mma16816(acc1[1][0], a[1], &bl[0]);
                mma16816(acc1[0][1], a[0], &bl[2]);  mma16816(acc1[1][1], a[1], &bl[2]);
            }
        }
        __syncthreads();   // last chunk MMA done; X region reusable for the X plane

        // ---- Phase C (X plane write) fused with Pass 2 (H-side gate GEMMs) ----
#pragma unroll
        for (int st = 0; st < 2; ++st)
#pragma unroll
            for (int ng = 0; ng < 2; ++ng) {
                int col = nb0 + 8 * ng + 2 * tq;
                int ra = rbase + 16 * st + g;
                int rb = ra + 8;
                float x0 = ftanh(acc1[st][ng][0] + B1[col]);
                float x1 = ftanh(acc1[st][ng][1] + B1[col + 1]);
                float x2 = ftanh(acc1[st][ng][2] + B1[col]);
                float x3 = ftanh(acc1[st][ng][3] + B1[col + 1]);
                uint32_t offa = (uint32_t)(ra * 128 + (((col >> 3) ^ (ra & 7)) << 4) + (col & 7) * 2);
                uint32_t offb = (uint32_t)(rb * 128 + (((col >> 3) ^ (rb & 7)) << 4) + (col & 7) * 2);
                *(uint32_t*)(XP + offa) = h2u(x0, x1);
                *(uint32_t*)(XP + offb) = h2u(x2, x3);
            }

        float ar[2][2][4], az[2][2][4], anh[2][2][4];
#pragma unroll
        for (int st = 0; st < 2; ++st)
#pragma unroll
            for (int ng = 0; ng < 2; ++ng)
#pragma unroll
                for (int e = 0; e < 4; ++e) { ar[st][ng][e] = az[st][ng][e] = anh[st][ng][e] = 0.0f; }

#pragma unroll
        for (int ks = 0; ks < 4; ++ks) {
            uint32_t ah[2][4];
#pragma unroll
            for (int st = 0; st < 2; ++st) {
                int row = rbase + 16 * st + rowa;
                uint32_t ro = (uint32_t)(row * 128 + (((ks * 2 + cca) ^ (row & 7)) << 4));
                ldsm4(ah[st], Hu + ro);
            }
            int gin = ks * 2 + binc;
            uint32_t no = (uint32_t)(nB * 128 + ((gin ^ (nB & 7)) << 4));
            uint32_t brh[4], bzh[4], bnh_[4], brl[4], bzl[4], bnl[4];
            ldsm4(brh,  Wu + 14 * TILE_B + no);
            ldsm4(bzh,  Wu + 15 * TILE_B + no);
            ldsm4(bnh_, Wu + 16 * TILE_B + no);
            ldsm4(brl,  Wu + 17 * TILE_B + no);
            ldsm4(bzl,  Wu + 18 * TILE_B + no);
            ldsm4(bnl,  Wu + 19 * TILE_B + no);
#pragma unroll
            for (int ng = 0; ng < 2; ++ng) {
                // spacing-6 emission: gate cycled, st inner
                mma16816(ar[0][ng],  ah[0], &brh[ng * 2]);  mma16816(ar[1][ng],  ah[1], &brh[ng * 2]);
                mma16816(az[0][ng],  ah[0], &bzh[ng * 2]);  mma16816(az[1][ng],  ah[1], &bzh[ng * 2]);
                mma16816(anh[0][ng], ah[0], &bnh_[ng * 2]); mma16816(anh[1][ng], ah[1], &bnh_[ng * 2]);
                mma16816(ar[0][ng],  ah[0], &brl[ng * 2]);  mma16816(ar[1][ng],  ah[1], &brl[ng * 2]);
                mma16816(az[0][ng],  ah[0], &bzl[ng * 2]);  mma16816(az[1][ng],  ah[1], &bzl[ng * 2]);
                mma16816(anh[0][ng], ah[0], &bnl[ng * 2]);  mma16816(anh[1][ng], ah[1], &bnl[ng * 2]);
            }
        }
        __syncthreads();   // X-plane writes visible; pass2 H reads done

        // ---- Pass 1: X-side gate GEMMs (slots 8..13) ----
        float ani[2][2][4];
#pragma unroll
        for (int st = 0; st < 2; ++st)
#pragma unroll
            for (int ng = 0; ng < 2; ++ng)
#pragma unroll
                for (int e = 0; e < 4; ++e) ani[st][ng][e] = 0.0f;

#pragma unroll
        for (int ks = 0; ks < 4; ++ks) {
            uint32_t ax[2][4];
#pragma unroll
            for (int st = 0; st < 2; ++st) {
                int row = rbase + 16 * st + rowa;
                uint32_t ro = (uint32_t)(row * 128 + (((ks * 2 + cca) ^ (row & 7)) << 4));
                ldsm4(ax[st], Xu + ro);
            }
            int gin = ks * 2 + binc;
            uint32_t no = (uint32_t)(nB * 128 + ((gin ^ (nB & 7)) << 4));
            uint32_t brh[4], bzh[4], bnh_[4], brl[4], bzl[4], bnl[4];
            ldsm4(brh,  Wu + 8  * TILE_B + no);
            ldsm4(bzh,  Wu + 9  * TILE_B + no);
            ldsm4(bnh_, Wu + 10 * TILE_B + no);
            ldsm4(brl,  Wu + 11 * TILE_B + no);
            ldsm4(bzl,  Wu + 12 * TILE_B + no);
            ldsm4(bnl,  Wu + 13 * TILE_B + no);
#pragma unroll
            for (int ng = 0; ng < 2; ++ng) {
                mma16816(ar[0][ng],  ax[0], &brh[ng * 2]);  mma16816(ar[1][ng],  ax[1], &brh[ng * 2]);
                mma16816(az[0][ng],  ax[0], &bzh[ng * 2]);  mma16816(az[1][ng],  ax[1], &bzh[ng * 2]);
                mma16816(ani[0][ng], ax[0], &bnh_[ng * 2]); mma16816(ani[1][ng], ax[1], &bnh_[ng * 2]);
                mma16816(ar[0][ng],  ax[0], &brl[ng * 2]);  mma16816(ar[1][ng],  ax[1], &brl[ng * 2]);
                mma16816(az[0][ng],  ax[0], &bzl[ng * 2]);  mma16816(az[1][ng],  ax[1], &bzl[ng * 2]);
                mma16816(ani[0][ng], ax[0], &bnl[ng * 2]);  mma16816(ani[1][ng], ax[1], &bnl[ng * 2]);
            }
        }
        __syncthreads();   // all X/H plane reads done (VP overlay + H-plane reuse safe)

        // ---- fused interval: epilogue(t) ∥ H-plane(t+1) ∥ obs prefetch(t+1) ----
        const int  ntile = tile + HCTA;
        const bool have_next = (ntile < ntiles);
        const int  nrow0 = ntile * 128;

        float4 nh[2][2];
        if (have_next) {
#pragma unroll
            for (int it = 0; it < 2; ++it) {
                int idx = tid + it * NT;
                int r = idx >> 3, gg = idx & 7;
                const float* p = hin + (size_t)(nrow0 + r) * 64 + gg * 8;
                nh[it][0] = *(const float4*)p;
                nh[it][1] = *(const float4*)(p + 4);
            }
            const float* p = obs + (size_t)(nrow0 + orow) * 256 + ogr * 8;
            pre0 = *(const float4*)p;
            pre1 = *(const float4*)(p + 4);
        }

        // batch hold + mask loads (gmem, L2-hot)
        float2 hold[2][2][2];
        int mk[4];
#pragma unroll
        for (int st = 0; st < 2; ++st) {
            mk[st * 2]     = mask[row0 + rbase + 16 * st + g];
            mk[st * 2 + 1] = mask[row0 + rbase + 16 * st + g + 8];
#pragma unroll
            for (int ng = 0; ng < 2; ++ng) {
                int cb = nb0 + 8 * ng + 2 * tq;
#pragma unroll
                for (int half = 0; half < 2; ++half) {
                    int row = rbase + 16 * st + g + 8 * half;
                    hold[st][ng][half] = *(const float2*)(hin + (size_t)(row0 + row) * 64 + cb);
                }
            }
        }

        float vp[4] = {0.0f, 0.0f, 0.0f, 0.0f};
#pragma unroll
        for (int st = 0; st < 2; ++st)
#pragma unroll
            for (int ng = 0; ng < 2; ++ng) {
                int cb = nb0 + 8 * ng + 2 * tq;
#pragma unroll
                for (int half = 0; half < 2; ++half) {
                    int row = rbase + 16 * st + g + 8 * half;
                    int m = mk[st * 2 + half];
                    float2 hv;
#pragma unroll
                    for (int e2 = 0; e2 < 2; ++e2) {
                        int e = 2 * half + e2;
                        int c = cb + e2;
                        float rr = fsigm(ar[st][ng][e] + BIH[c] + BHH[c]);
                        float zz = fsigm(az[st][ng][e] + BIH[64 + c] + BHH[64 + c]);
                        float nn = ftanh(ani[st][ng][e] + BIH[128 + c] +
                                         rr * (anh[st][ng][e] + BHH[128 + c]));
                        float ho = e2 ? hold[st][ng][half].y : hold[st][ng][half].x;
                        float hg = (1.0f - zz) * nn + zz * ho;
                        float hn = m ? hg : ho;
                        if (e2) hv.y = hn; else hv.x = hn;
                        vp[st * 2 + half] += hn * W2[c];
                    }
                    *(float2*)(hout + (size_t)(row0 + row) * 64 + cb) = hv;
                }
            }

#pragma unroll
        for (int off = 1; off <= 2; off <<= 1)
#pragma unroll
            for (int q = 0; q < 4; ++q) vp[q] += __shfl_xor_sync(0xffffffffu, vp[q], off);
        if (tq == 0) {
#pragma unroll
            for (int st = 0; st < 2; ++st) {
                VP[(rbase + 16 * st + g) * 4 + nq]     = vp[st * 2];
                VP[(rbase + 16 * st + g + 8) * 4 + nq] = vp[st * 2 + 1];
            }
        }

        // H plane(t+1): convert + store (H plane free since pass2)
        if (have_next) {
#pragma unroll
            for (int it = 0; it < 2; ++it) {
                int idx = tid + it * NT;
                int r = idx >> 3, gg = idx & 7;
                uint4 u;
                u.x = h2u(nh[it][0].x, nh[it][0].y);  u.y = h2u(nh[it][0].z, nh[it][0].w);
                u.z = h2u(nh[it][1].x, nh[it][1].y);  u.w = h2u(nh[it][1].z, nh[it][1].w);
                uint32_t off = (uint32_t)(r * 128 + ((gg ^ (r & 7)) << 4));
                *(uint4*)(HP + off) = u;
            }
        }
        __syncthreads();   // VP visible; H plane(t+1) ready

        if (tid < 128)
            vout[row0 + tid] = VP[tid * 4] + VP[tid * 4 + 1] + VP[tid * 4 + 2] + VP[tid * 4 + 3] + bias2;
    }
}

// ---------------- launch ----------------
extern "C" void kernel_launch(void* const* d_in, const int* in_sizes, int n_in,
                              void* d_out, int out_size) {
    const float* obs = (const float*)d_in[0];
    const float* h1  = (const float*)d_in[1];
    const float* h2  = (const float*)d_in[2];
    const int*   msk = (const int*)d_in[3];

    const int B = in_sizes[1] / 64;   // 262144
    const int ntiles = B / 128;       // 2048

    float* out = (float*)d_out;
    float* v1  = out;
    float* v2  = out + (size_t)B;
    float* ho1 = out + 2 * (size_t)B;
    float* ho2 = ho1 + (size_t)B * 64;

    convert_weights_kernel<<<160, 256>>>(
        (const float*)d_in[4],  (const float*)d_in[6],  (const float*)d_in[7],
        (const float*)d_in[12], (const float*)d_in[14], (const float*)d_in[15]);

    cudaFuncSetAttribute(gru_hmma_kernel,
                         cudaFuncAttributeMaxDynamicSharedMemorySize, SMEM_TOTAL);

    gru_hmma_kernel<<<NCTA, NT, SMEM_TOTAL>>>(
        obs, h1, h2, msk,
        (const float*)d_in[8],  (const float*)d_in[9],
        (const float*)d_in[5],  (const float*)d_in[10], (const float*)d_in[11],
        (const float*)d_in[16], (const float*)d_in[17],
        (const float*)d_in[13], (const float*)d_in[18], (const float*)d_in[19],
        v1, v2, ho1, ho2, ntiles);
}

// round 14
// speedup vs baseline: 1.1801x; 1.0170x over previous
#include <cuda_runtime.h>
#include <cuda_fp16.h>
#include <stdint.h>

#define NT 512
#define NCTA 148
#define HCTA 74

// ---------------- math helpers ----------------
__device__ __forceinline__ float fsigm(float x) { return __fdividef(1.0f, 1.0f + __expf(-x)); }
__device__ __forceinline__ float ftanh(float x) {
    return 1.0f - __fdividef(2.0f, __expf(2.0f * x) + 1.0f);
}
__device__ __forceinline__ uint32_t h2u(float a, float b) {   // lo=a, hi=b
    __half2 h = __floats2half2_rn(a, b);
    return *(uint32_t*)&h;
}
__device__ __forceinline__ uint32_t smem_u32(const void* p) {
    uint32_t a;
    asm("{ .reg .u64 t; cvta.to.shared.u64 t, %1; cvt.u32.u64 %0, t; }" : "=r"(a) : "l"(p));
    return a;
}

// ---------------- mma (fp16 in, fp32 acc) + ldmatrix ----------------
__device__ __forceinline__ void mma16816(float* c, const uint32_t* a, const uint32_t* b) {
    asm volatile(
        "mma.sync.aligned.m16n8k16.row.col.f32.f16.f16.f32 "
        "{%0,%1,%2,%3}, {%4,%5,%6,%7}, {%8,%9}, {%0,%1,%2,%3};"
        : "+f"(c[0]), "+f"(c[1]), "+f"(c[2]), "+f"(c[3])
        : "r"(a[0]), "r"(a[1]), "r"(a[2]), "r"(a[3]), "r"(b[0]), "r"(b[1]));
}
__device__ __forceinline__ void ldsm4(uint32_t* d, uint32_t addr) {
    asm volatile("ldmatrix.sync.aligned.m8n8.x4.shared.b16 {%0,%1,%2,%3}, [%4];"
                 : "=r"(d[0]), "=r"(d[1]), "=r"(d[2]), "=r"(d[3]) : "r"(addr));
}

// ---------------- weight scratch: swizzled [64][64] fp16 tiles, 8KB each ------
// half-index for (row n, col k): n*64 + ((k>>3 ^ (n&7))<<3) + (k&7)
#define TILE_B 8192
#define TILE_H 4096
__device__ __align__(16) __half g_wt[2][20][TILE_H];

__global__ void convert_weights_kernel(
    const float* __restrict__ fc1a, const float* __restrict__ wiha, const float* __restrict__ whha,
    const float* __restrict__ fc1b, const float* __restrict__ wihb, const float* __restrict__ whhb)
{
    int tid = blockIdx.x * blockDim.x + threadIdx.x;
    int stride = gridDim.x * blockDim.x;
    for (int s = 0; s < 2; ++s) {
        const float* fc1 = s ? fc1b : fc1a;
        const float* wih = s ? wihb : wiha;
        const float* whh = s ? whhb : whha;
        for (int e = tid; e < 40960; e += stride) {
            float v; int th, tl, n, k;
            if (e < 16384) {                        // fc1 [64,256] -> tiles 0..7
                n = e >> 8; int kf = e & 255; int kc = kf >> 6; k = kf & 63;
                v = fc1[e]; th = kc; tl = 4 + kc;
            } else if (e < 28672) {                 // wih [192,64] -> tiles 8..13
                int e2 = e - 16384, j = e2 >> 6; k = e2 & 63; int gg = j >> 6; n = j & 63;
                v = wih[e2]; th = 8 + gg; tl = 11 + gg;
            } else {                                // whh [192,64] -> tiles 14..19
                int e2 = e - 28672, j = e2 >> 6; k = e2 & 63; int gg = j >> 6; n = j & 63;
                v = whh[e2]; th = 14 + gg; tl = 17 + gg;
            }
            uint32_t off = n * 64 + (((k >> 3) ^ (n & 7)) << 3) + (k & 7);
            __half hi = __float2half_rn(v);
            __half lo = __float2half_rn(v - __half2float(hi));
            g_wt[s][th][off] = hi;
            g_wt[s][tl][off] = lo;
        }
    }
}

// ---------------- smem layout (bytes) ----------------
#define SM_W    0                 // 20 tiles = 163840
#define SM_X    163840            // Phase B: buf0 @+0 (16KB), buf1 @+16384 (16KB)
                                  // Phase C/E: X plane @+0 (16KB); VP @+24576
#define SM_H    196608            // H plane [128 rows][128 B] = 16KB
#define SM_BIH  212992            // float[192]
#define SM_BHH  213760            // float[192]
#define SM_B1   214528            // float[64]
#define SM_W2   214784            // float[64]
#define SMEM_TOTAL 215040

__global__ __launch_bounds__(NT, 1)
void gru_hmma_kernel(
    const float* __restrict__ obs, const float* __restrict__ h1, const float* __restrict__ h2,
    const int* __restrict__ mask,
    const float* __restrict__ bih1, const float* __restrict__ bhh1,
    const float* __restrict__ bfc1_1, const float* __restrict__ wfc2_1, const float* __restrict__ bfc2_1,
    const float* __restrict__ bih2, const float* __restrict__ bhh2,
    const float* __restrict__ bfc1_2, const float* __restrict__ wfc2_2, const float* __restrict__ bfc2_2,
    float* __restrict__ v1, float* __restrict__ v2,
    float* __restrict__ ho1, float* __restrict__ ho2,
    int ntiles)
{
    extern __shared__ __align__(16) unsigned char sm[];
    unsigned char* XP = sm + SM_X;          // X plane (post-B)
    unsigned char* HP = sm + SM_H;          // H plane
    float* VP  = (float*)(sm + SM_X + 24576);
    float* BIH = (float*)(sm + SM_BIH);
    float* BHH = (float*)(sm + SM_BHH);
    float* B1  = (float*)(sm + SM_B1);
    float* W2  = (float*)(sm + SM_W2);

    const int tid  = threadIdx.x;
    const int lane = tid & 31;
    const int wid  = tid >> 5;
    const int g    = lane >> 2;
    const int tq   = lane & 3;

    const int ms  = wid & 3;
    const int nq  = wid >> 2;
    const int rbase = 32 * ms;
    const int nb0   = 16 * nq;

    // ldmatrix per-lane components
    const int rowa = (lane & 7) + 8 * ((lane >> 3) & 1);   // A frag row within 16-strip
    const int cca  = lane >> 4;                             // A granule sub (0,1)
    const int nB   = nb0 + ((lane >> 4) << 3) + (lane & 7); // B x4 row (both ng)
    const int binc = (lane >> 3) & 1;                       // B granule sub

    const uint32_t smb = smem_u32(sm);
    const uint32_t Wu  = smb + SM_W;
    const uint32_t Xu  = smb + SM_X;
    const uint32_t Hu  = smb + SM_H;

    const int stream = (blockIdx.x >= HCTA) ? 1 : 0;
    const int local  = blockIdx.x - HCTA * stream;

    const float* hin = stream ? h2 : h1;
    const float* bih = stream ? bih2 : bih1;
    const float* bhh = stream ? bhh2 : bhh1;
    const float* bf1 = stream ? bfc1_2 : bfc1_1;
    const float* wf2 = stream ? wfc2_2 : wfc2_1;
    const float* bf2 = stream ? bfc2_2 : bfc2_1;
    float* vout = stream ? v2 : v1;
    float* hout = stream ? ho2 : ho1;

    // obs/H-conversion task: thread owns (row cr[it], granule cg[it]) per 64-col chunk
    const int cr0 = tid >> 3,        cg0 = tid & 7;          // it=0
    const int cr1 = (tid + NT) >> 3, cg1 = (tid + NT) & 7;   // it=1
    const uint32_t csoff0 = (uint32_t)(cr0 * 128 + ((cg0 ^ (cr0 & 7)) << 4));
    const uint32_t csoff1 = (uint32_t)(cr1 * 128 + ((cg1 ^ (cr1 & 7)) << 4));

    // ---- one-time: all 20 weight tiles + biases into smem ----
    {
        const int4* src = (const int4*)&g_wt[stream][0][0];
        int4* dst = (int4*)sm;
        for (int i = tid; i < (20 * TILE_B) / 16; i += NT) dst[i] = src[i];
    }
    for (int i = tid; i < 192; i += NT) { BIH[i] = bih[i]; BHH[i] = bhh[i]; }
    if (tid < 64) { B1[tid] = bf1[tid]; W2[tid] = wf2[tid]; }
    const float bias2 = bf2[0];
    __syncthreads();

    // ---- prologue: first tile H plane + obs chunk0 prefetch ----
    float4 pre[2][2];
    {
        const int row0 = local * 128;
#pragma unroll
        for (int it = 0; it < 2; ++it) {
            int r = it ? cr1 : cr0, gg = it ? cg1 : cg0;
            const float* p = hin + (size_t)(row0 + r) * 64 + gg * 8;
            float4 v0 = *(const float4*)p;
            float4 v1 = *(const float4*)(p + 4);
            uint4 u;
            u.x = h2u(v0.x, v0.y);  u.y = h2u(v0.z, v0.w);
            u.z = h2u(v1.x, v1.y);  u.w = h2u(v1.z, v1.w);
            *(uint4*)(HP + (it ? csoff1 : csoff0)) = u;
        }
#pragma unroll
        for (int it = 0; it < 2; ++it) {
            int r = it ? cr1 : cr0, gg = it ? cg1 : cg0;
            const float* p = obs + (size_t)(row0 + r) * 256 + gg * 8;
            pre[it][0] = *(const float4*)p;
            pre[it][1] = *(const float4*)(p + 4);
        }
    }

    for (int tile = local; tile < ntiles; tile += HCTA) {
        const int row0 = tile * 128;

        // ---- Phase B: fc1 GEMM, K=256 in 4 chunks of 64, double-buffered ----
        float acc1[2][2][4];
#pragma unroll
        for (int st = 0; st < 2; ++st)
#pragma unroll
            for (int ng = 0; ng < 2; ++ng)
#pragma unroll
                for (int e = 0; e < 4; ++e) acc1[st][ng][e] = 0.0f;

        for (int kc = 0; kc < 4; ++kc) {
            {
                unsigned char* bb = sm + SM_X + (kc & 1) * 16384;
#pragma unroll
                for (int it = 0; it < 2; ++it) {
                    uint4 u;
                    u.x = h2u(pre[it][0].x, pre[it][0].y);  u.y = h2u(pre[it][0].z, pre[it][0].w);
                    u.z = h2u(pre[it][1].x, pre[it][1].y);  u.w = h2u(pre[it][1].z, pre[it][1].w);
                    *(uint4*)(bb + (it ? csoff1 : csoff0)) = u;
                }
            }
            if (kc < 3) {
#pragma unroll
                for (int it = 0; it < 2; ++it) {
                    int r = it ? cr1 : cr0, gg = it ? cg1 : cg0;
                    const float* p = obs + (size_t)(row0 + r) * 256 + (kc + 1) * 64 + gg * 8;
                    pre[it][0] = *(const float4*)p;
                    pre[it][1] = *(const float4*)(p + 4);
                }
            }
            __syncthreads();

            const uint32_t buf = Xu + (uint32_t)((kc & 1) * 16384);
            const uint32_t bth = Wu + (uint32_t)kc * TILE_B;
            const uint32_t btl = bth + 4 * TILE_B;
#pragma unroll
            for (int ks = 0; ks < 4; ++ks) {
                uint32_t a[2][4], bh[4], bl[4];
#pragma unroll
                for (int st = 0; st < 2; ++st) {
                    int row = rbase + 16 * st + rowa;
                    uint32_t ro = (uint32_t)(row * 128 + (((ks * 2 + cca) ^ (row & 7)) << 4));
                    ldsm4(a[st], buf + ro);
                }
                int gin = ks * 2 + binc;
                uint32_t no = (uint32_t)(nB * 128 + ((gin ^ (nB & 7)) << 4));
                ldsm4(bh, bth + no);
                ldsm4(bl, btl + no);
                mma16816(acc1[0][0], a[0], &bh[0]);  mma16816(acc1[1][0], a[1], &bh[0]);
                mma16816(acc1[0][1], a[0], &bh[2]);  mma16816(acc1[1][1], a[1], &bh[2]);
                mma16816(acc1[0][0], a[0], &bl[0]);  mma16816(acc1[1][0], a[1], &bl[0]);
                mma16816(acc1[0][1], a[0], &bl[2]);  mma16816(acc1[1][1], a[1], &bl[2]);
            }
        }
        __syncthreads();   // last chunk MMA done; X region reusable for the X plane

        // ---- Phase C (X plane write) fused with Pass 2 (H-side gate GEMMs) ----
#pragma unroll
        for (int st = 0; st < 2; ++st)
#pragma unroll
            for (int ng = 0; ng < 2; ++ng) {
                int col = nb0 + 8 * ng + 2 * tq;
                int ra = rbase + 16 * st + g;
                int rb = ra + 8;
                float x0 = ftanh(acc1[st][ng][0] + B1[col]);
                float x1 = ftanh(acc1[st][ng][1] + B1[col + 1]);
                float x2 = ftanh(acc1[st][ng][2] + B1[col]);
                float x3 = ftanh(acc1[st][ng][3] + B1[col + 1]);
                uint32_t offa = (uint32_t)(ra * 128 + (((col >> 3) ^ (ra & 7)) << 4) + (col & 7) * 2);
                uint32_t offb = (uint32_t)(rb * 128 + (((col >> 3) ^ (rb & 7)) << 4) + (col & 7) * 2);
                *(uint32_t*)(XP + offa) = h2u(x0, x1);
                *(uint32_t*)(XP + offb) = h2u(x2, x3);
            }

        float ar[2][2][4], az[2][2][4], anh[2][2][4];
#pragma unroll
        for (int st = 0; st < 2; ++st)
#pragma unroll
            for (int ng = 0; ng < 2; ++ng)
#pragma unroll
                for (int e = 0; e < 4; ++e) { ar[st][ng][e] = az[st][ng][e] = anh[st][ng][e] = 0.0f; }

#pragma unroll
        for (int ks = 0; ks < 4; ++ks) {
            uint32_t ah[2][4];
#pragma unroll
            for (int st = 0; st < 2; ++st) {
                int row = rbase + 16 * st + rowa;
                uint32_t ro = (uint32_t)(row * 128 + (((ks * 2 + cca) ^ (row & 7)) << 4));
                ldsm4(ah[st], Hu + ro);
            }
            int gin = ks * 2 + binc;
            uint32_t no = (uint32_t)(nB * 128 + ((gin ^ (nB & 7)) << 4));
            uint32_t brh[4], bzh[4], bnh_[4], brl[4], bzl[4], bnl[4];
            ldsm4(brh,  Wu + 14 * TILE_B + no);
            ldsm4(bzh,  Wu + 15 * TILE_B + no);
            ldsm4(bnh_, Wu + 16 * TILE_B + no);
            ldsm4(brl,  Wu + 17 * TILE_B + no);
            ldsm4(bzl,  Wu + 18 * TILE_B + no);
            ldsm4(bnl,  Wu + 19 * TILE_B + no);
#pragma unroll
            for (int ng = 0; ng < 2; ++ng) {
                mma16816(ar[0][ng],  ah[0], &brh[ng * 2]);  mma16816(ar[1][ng],  ah[1], &brh[ng * 2]);
                mma16816(az[0][ng],  ah[0], &bzh[ng * 2]);  mma16816(az[1][ng],  ah[1], &bzh[ng * 2]);
                mma16816(anh[0][ng], ah[0], &bnh_[ng * 2]); mma16816(anh[1][ng], ah[1], &bnh_[ng * 2]);
                mma16816(ar[0][ng],  ah[0], &brl[ng * 2]);  mma16816(ar[1][ng],  ah[1], &brl[ng * 2]);
                mma16816(az[0][ng],  ah[0], &bzl[ng * 2]);  mma16816(az[1][ng],  ah[1], &bzl[ng * 2]);
                mma16816(anh[0][ng], ah[0], &bnl[ng * 2]);  mma16816(anh[1][ng], ah[1], &bnl[ng * 2]);
            }
        }
        __syncthreads();   // X-plane writes visible; pass2 H reads done

        // ---- Pass 1: X-side gate GEMMs (slots 8..13) ----
        float ani[2][2][4];
#pragma unroll
        for (int st = 0; st < 2; ++st)
#pragma unroll
            for (int ng = 0; ng < 2; ++ng)
#pragma unroll
                for (int e = 0; e < 4; ++e) ani[st][ng][e] = 0.0f;

#pragma unroll
        for (int ks = 0; ks < 4; ++ks) {
            uint32_t ax[2][4];
#pragma unroll
            for (int st = 0; st < 2; ++st) {
                int row = rbase + 16 * st + rowa;
                uint32_t ro = (uint32_t)(row * 128 + (((ks * 2 + cca) ^ (row & 7)) << 4));
                ldsm4(ax[st], Xu + ro);
            }
            int gin = ks * 2 + binc;
            uint32_t no = (uint32_t)(nB * 128 + ((gin ^ (nB & 7)) << 4));
            uint32_t brh[4], bzh[4], bnh_[4], brl[4], bzl[4], bnl[4];
            ldsm4(brh,  Wu + 8  * TILE_B + no);
            ldsm4(bzh,  Wu + 9  * TILE_B + no);
            ldsm4(bnh_, Wu + 10 * TILE_B + no);
            ldsm4(brl,  Wu + 11 * TILE_B + no);
            ldsm4(bzl,  Wu + 12 * TILE_B + no);
            ldsm4(bnl,  Wu + 13 * TILE_B + no);
#pragma unroll
            for (int ng = 0; ng < 2; ++ng) {
                mma16816(ar[0][ng],  ax[0], &brh[ng * 2]);  mma16816(ar[1][ng],  ax[1], &brh[ng * 2]);
                mma16816(az[0][ng],  ax[0], &bzh[ng * 2]);  mma16816(az[1][ng],  ax[1], &bzh[ng * 2]);
                mma16816(ani[0][ng], ax[0], &bnh_[ng * 2]); mma16816(ani[1][ng], ax[1], &bnh_[ng * 2]);
                mma16816(ar[0][ng],  ax[0], &brl[ng * 2]);  mma16816(ar[1][ng],  ax[1], &brl[ng * 2]);
                mma16816(az[0][ng],  ax[0], &bzl[ng * 2]);  mma16816(az[1][ng],  ax[1], &bzl[ng * 2]);
                mma16816(ani[0][ng], ax[0], &bnl[ng * 2]);  mma16816(ani[1][ng], ax[1], &bnl[ng * 2]);
            }
        }
        __syncthreads();   // all X/H plane reads done (VP overlay + H-plane reuse safe)

        // ---- fused interval: epilogue(t) ∥ H-plane(t+1) ∥ obs prefetch(t+1) ----
        const int  ntile = tile + HCTA;
        const bool have_next = (ntile < ntiles);
        const int  nrow0 = ntile * 128;

        float4 nh[2][2];
        if (have_next) {
#pragma unroll
            for (int it = 0; it < 2; ++it) {
                int r = it ? cr1 : cr0, gg = it ? cg1 : cg0;
                const float* p = hin + (size_t)(nrow0 + r) * 64 + gg * 8;
                nh[it][0] = *(const float4*)p;
                nh[it][1] = *(const float4*)(p + 4);
            }
        }

        // batch hold + mask loads (gmem, L2-hot)
        float2 hold[2][2][2];
        int mk[4];
#pragma unroll
        for (int st = 0; st < 2; ++st) {
            mk[st * 2]     = mask[row0 + rbase + 16 * st + g];
            mk[st * 2 + 1] = mask[row0 + rbase + 16 * st + g + 8];
#pragma unroll
            for (int ng = 0; ng < 2; ++ng) {
                int cb = nb0 + 8 * ng + 2 * tq;
#pragma unroll
                for (int half = 0; half < 2; ++half) {
                    int row = rbase + 16 * st + g + 8 * half;
                    hold[st][ng][half] = *(const float2*)(hin + (size_t)(row0 + row) * 64 + cb);
                }
            }
        }

        float vp[4] = {0.0f, 0.0f, 0.0f, 0.0f};
#pragma unroll
        for (int st = 0; st < 2; ++st)
#pragma unroll
            for (int ng = 0; ng < 2; ++ng) {
                int cb = nb0 + 8 * ng + 2 * tq;
#pragma unroll
                for (int half = 0; half < 2; ++half) {
                    int row = rbase + 16 * st + g + 8 * half;
                    int m = mk[st * 2 + half];
                    float2 hv;
#pragma unroll
                    for (int e2 = 0; e2 < 2; ++e2) {
                        int e = 2 * half + e2;
                        int c = cb + e2;
                        float rr = fsigm(ar[st][ng][e] + BIH[c] + BHH[c]);
                        float zz = fsigm(az[st][ng][e] + BIH[64 + c] + BHH[64 + c]);
                        float nn = ftanh(ani[st][ng][e] + BIH[128 + c] +
                                         rr * (anh[st][ng][e] + BHH[128 + c]));
                        float ho = e2 ? hold[st][ng][half].y : hold[st][ng][half].x;
                        float hg = (1.0f - zz) * nn + zz * ho;
                        float hn = m ? hg : ho;
                        if (e2) hv.y = hn; else hv.x = hn;
                        vp[st * 2 + half] += hn * W2[c];
                    }
                    *(float2*)(hout + (size_t)(row0 + row) * 64 + cb) = hv;
                }
            }

        // next-tile obs chunk0 prefetch (overlaps reduce + H-plane conversion)
        if (have_next) {
#pragma unroll
            for (int it = 0; it < 2; ++it) {
                int r = it ? cr1 : cr0, gg = it ? cg1 : cg0;
                const float* p = obs + (size_t)(nrow0 + r) * 256 + gg * 8;
                pre[it][0] = *(const float4*)p;
                pre[it][1] = *(const float4*)(p + 4);
            }
        }

#pragma unroll
        for (int off = 1; off <= 2; off <<= 1)
#pragma unroll
            for (int q = 0; q < 4; ++q) vp[q] += __shfl_xor_sync(0xffffffffu, vp[q], off);
        if (tq == 0) {
#pragma unroll
            for (int st = 0; st < 2; ++st) {
                VP[(rbase + 16 * st + g) * 4 + nq]     = vp[st * 2];
                VP[(rbase + 16 * st + g + 8) * 4 + nq] = vp[st * 2 + 1];
            }
        }

        // H plane(t+1): convert + store (H plane free since pass2)
        if (have_next) {
#pragma unroll
            for (int it = 0; it < 2; ++it) {
                uint4 u;
                u.x = h2u(nh[it][0].x, nh[it][0].y);  u.y = h2u(nh[it][0].z, nh[it][0].w);
                u.z = h2u(nh[it][1].x, nh[it][1].y);  u.w = h2u(nh[it][1].z, nh[it][1].w);
                *(uint4*)(HP + (it ? csoff1 : csoff0)) = u;
            }
        }
        __syncthreads();   // VP visible; H plane(t+1) ready

        if (tid < 128)
            vout[row0 + tid] = VP[tid * 4] + VP[tid * 4 + 1] + VP[tid * 4 + 2] + VP[tid * 4 + 3] + bias2;
    }
}

// ---------------- launch ----------------
extern "C" void kernel_launch(void* const* d_in, const int* in_sizes, int n_in,
                              void* d_out, int out_size) {
    const float* obs = (const float*)d_in[0];
    const float* h1  = (const float*)d_in[1];
    const float* h2  = (const float*)d_in[2];
    const int*   msk = (const int*)d_in[3];

    const int B = in_sizes[1] / 64;   // 262144
    const int ntiles = B / 128;       // 2048

    float* out = (float*)d_out;
    float* v1  = out;
    float* v2  = out + (size_t)B;
    float* ho1 = out + 2 * (size_t)B;
    float* ho2 = ho1 + (size_t)B * 64;

    convert_weights_kernel<<<160, 256>>>(
        (const float*)d_in[4],  (const float*)d_in[6],  (const float*)d_in[7],
        (const float*)d_in[12], (const float*)d_in[14], (const float*)d_in[15]);

    cudaFuncSetAttribute(gru_hmma_kernel,
                         cudaFuncAttributeMaxDynamicSharedMemorySize, SMEM_TOTAL);

    gru_hmma_kernel<<<NCTA, NT, SMEM_TOTAL>>>(
        obs, h1, h2, msk,
        (const float*)d_in[8],  (const float*)d_in[9],
        (const float*)d_in[5],  (const float*)d_in[10], (const float*)d_in[11],
        (const float*)d_in[16], (const float*)d_in[17],
        (const float*)d_in[13], (const float*)d_in[18], (const float*)d_in[19],
        v1, v2, ho1, ho2, ntiles);
}

// round 15
// speedup vs baseline: 1.1979x; 1.0150x over previous
#include <cuda_runtime.h>
#include <cuda_fp16.h>
#include <stdint.h>

#define NT 512
#define NCTA 148
#define HCTA 74

// ---------------- math helpers ----------------
__device__ __forceinline__ float fsigm(float x) { return __fdividef(1.0f, 1.0f + __expf(-x)); }
__device__ __forceinline__ float ftanh(float x) {
    return 1.0f - __fdividef(2.0f, __expf(2.0f * x) + 1.0f);
}
__device__ __forceinline__ uint32_t h2u(float a, float b) {   // lo=a, hi=b
    __half2 h = __floats2half2_rn(a, b);
    return *(uint32_t*)&h;
}
__device__ __forceinline__ uint32_t smem_u32(const void* p) {
    uint32_t a;
    asm("{ .reg .u64 t; cvta.to.shared.u64 t, %1; cvt.u32.u64 %0, t; }" : "=r"(a) : "l"(p));
    return a;
}

// ---------------- mma (fp16 in, fp32 acc) + ldmatrix ----------------
__device__ __forceinline__ void mma16816(float* c, const uint32_t* a, const uint32_t* b) {
    asm volatile(
        "mma.sync.aligned.m16n8k16.row.col.f32.f16.f16.f32 "
        "{%0,%1,%2,%3}, {%4,%5,%6,%7}, {%8,%9}, {%0,%1,%2,%3};"
        : "+f"(c[0]), "+f"(c[1]), "+f"(c[2]), "+f"(c[3])
        : "r"(a[0]), "r"(a[1]), "r"(a[2]), "r"(a[3]), "r"(b[0]), "r"(b[1]));
}
__device__ __forceinline__ void ldsm4(uint32_t* d, uint32_t addr) {
    asm volatile("ldmatrix.sync.aligned.m8n8.x4.shared.b16 {%0,%1,%2,%3}, [%4];"
                 : "=r"(d[0]), "=r"(d[1]), "=r"(d[2]), "=r"(d[3]) : "r"(addr));
}
#define GROUP_BAR(id) asm volatile("bar.sync %0, 128;" :: "r"(id) : "memory")

// ---------------- weight scratch: swizzled [64][64] fp16 tiles, 8KB each ------
#define TILE_B 8192
#define TILE_H 4096
__device__ __align__(16) __half g_wt[2][20][TILE_H];

__global__ void convert_weights_kernel(
    const float* __restrict__ fc1a, const float* __restrict__ wiha, const float* __restrict__ whha,
    const float* __restrict__ fc1b, const float* __restrict__ wihb, const float* __restrict__ whhb)
{
    int tid = blockIdx.x * blockDim.x + threadIdx.x;
    int stride = gridDim.x * blockDim.x;
    for (int s = 0; s < 2; ++s) {
        const float* fc1 = s ? fc1b : fc1a;
        const float* wih = s ? wihb : wiha;
        const float* whh = s ? whhb : whha;
        for (int e = tid; e < 40960; e += stride) {
            float v; int th, tl, n, k;
            if (e < 16384) {                        // fc1 [64,256] -> tiles 0..7
                n = e >> 8; int kf = e & 255; int kc = kf >> 6; k = kf & 63;
                v = fc1[e]; th = kc; tl = 4 + kc;
            } else if (e < 28672) {                 // wih [192,64] -> tiles 8..13
                int e2 = e - 16384, j = e2 >> 6; k = e2 & 63; int gg = j >> 6; n = j & 63;
                v = wih[e2]; th = 8 + gg; tl = 11 + gg;
            } else {                                // whh [192,64] -> tiles 14..19
                int e2 = e - 28672, j = e2 >> 6; k = e2 & 63; int gg = j >> 6; n = j & 63;
                v = whh[e2]; th = 14 + gg; tl = 17 + gg;
            }
            uint32_t off = n * 64 + (((k >> 3) ^ (n & 7)) << 3) + (k & 7);
            __half hi = __float2half_rn(v);
            __half lo = __float2half_rn(v - __half2float(hi));
            g_wt[s][th][off] = hi;
            g_wt[s][tl][off] = lo;
        }
    }
}

// ---------------- smem layout (bytes) ----------------
#define SM_W    0                 // 20 tiles = 163840
#define SM_X    163840            // Phase B: buf0 @+0 (16KB), buf1 @+16384 (16KB)
                                  // Phase C/E: X plane @+0 (16KB); VP @+24576
#define SM_H    196608            // H plane [128 rows][128 B] = 16KB
#define SM_BRZ  212992            // float[128]: folded r,z biases (BIH+BHH)
#define SM_BNI  213504            // float[64]:  BIH n
#define SM_BNH  213760            // float[64]:  BHH n
#define SM_B1   214528            // float[64]
#define SM_W2   214784            // float[64]
#define SMEM_TOTAL 215040

__global__ __launch_bounds__(NT, 1)
void gru_hmma_kernel(
    const float* __restrict__ obs, const float* __restrict__ h1, const float* __restrict__ h2,
    const int* __restrict__ mask,
    const float* __restrict__ bih1, const float* __restrict__ bhh1,
    const float* __restrict__ bfc1_1, const float* __restrict__ wfc2_1, const float* __restrict__ bfc2_1,
    const float* __restrict__ bih2, const float* __restrict__ bhh2,
    const float* __restrict__ bfc1_2, const float* __restrict__ wfc2_2, const float* __restrict__ bfc2_2,
    float* __restrict__ v1, float* __restrict__ v2,
    float* __restrict__ ho1, float* __restrict__ ho2,
    int ntiles)
{
    extern __shared__ __align__(16) unsigned char sm[];
    unsigned char* XP = sm + SM_X;          // X plane (post-B)
    unsigned char* HP = sm + SM_H;          // H plane
    float* VP  = (float*)(sm + SM_X + 24576);
    float* BRZ = (float*)(sm + SM_BRZ);
    float* BNI = (float*)(sm + SM_BNI);
    float* BNH = (float*)(sm + SM_BNH);
    float* B1  = (float*)(sm + SM_B1);
    float* W2  = (float*)(sm + SM_W2);

    const int tid  = threadIdx.x;
    const int lane = tid & 31;
    const int wid  = tid >> 5;
    const int g    = lane >> 2;
    const int tq   = lane & 3;

    const int ms  = wid & 3;
    const int nq  = wid >> 2;
    const int rbase = 32 * ms;
    const int nb0   = 16 * nq;

    // ldmatrix per-lane components
    const int rowa = (lane & 7) + 8 * ((lane >> 3) & 1);
    const int cca  = lane >> 4;
    const int nB   = nb0 + ((lane >> 4) << 3) + (lane & 7);
    const int binc = (lane >> 3) & 1;

    const uint32_t smb = smem_u32(sm);
    const uint32_t Wu  = smb + SM_W;
    const uint32_t Xu  = smb + SM_X;
    const uint32_t Hu  = smb + SM_H;

    const int stream = (blockIdx.x >= HCTA) ? 1 : 0;
    const int local  = blockIdx.x - HCTA * stream;

    const float* hin = stream ? h2 : h1;
    const float* bih = stream ? bih2 : bih1;
    const float* bhh = stream ? bhh2 : bhh1;
    const float* bf1 = stream ? bfc1_2 : bfc1_1;
    const float* wf2 = stream ? wfc2_2 : wfc2_1;
    const float* bf2 = stream ? bfc2_2 : bfc2_1;
    float* vout = stream ? v2 : v1;
    float* hout = stream ? ho2 : ho1;

    // obs/H-conversion task: thread owns (row cr[it], granule cg[it]) per 64-col chunk
    const int cr0 = tid >> 3,        cg0 = tid & 7;
    const int cr1 = (tid + NT) >> 3, cg1 = (tid + NT) & 7;
    const uint32_t csoff0 = (uint32_t)(cr0 * 128 + ((cg0 ^ (cr0 & 7)) << 4));
    const uint32_t csoff1 = (uint32_t)(cr1 * 128 + ((cg1 ^ (cr1 & 7)) << 4));

    // ---- one-time: all 20 weight tiles + biases into smem ----
    {
        const int4* src = (const int4*)&g_wt[stream][0][0];
        int4* dst = (int4*)sm;
        for (int i = tid; i < (20 * TILE_B) / 16; i += NT) dst[i] = src[i];
    }
    if (tid < 128) BRZ[tid] = bih[tid] + bhh[tid];            // r (0..63), z (64..127)
    else if (tid < 192) BNI[tid - 128] = bih[tid];            // n input bias
    else if (tid < 256) BNH[tid - 192] = bhh[tid - 64];       // n hidden bias
    if (tid < 64) { B1[tid] = bf1[tid]; W2[tid] = wf2[tid]; }
    const float bias2 = bf2[0];
    __syncthreads();

    // ---- prologue: first tile H plane + obs chunk0 prefetch ----
    float4 pre[2][2];
    {
        const int row0 = local * 128;
#pragma unroll
        for (int it = 0; it < 2; ++it) {
            int r = it ? cr1 : cr0, gg = it ? cg1 : cg0;
            const float* p = hin + (size_t)(row0 + r) * 64 + gg * 8;
            float4 v0 = *(const float4*)p;
            float4 v1 = *(const float4*)(p + 4);
            uint4 u;
            u.x = h2u(v0.x, v0.y);  u.y = h2u(v0.z, v0.w);
            u.z = h2u(v1.x, v1.y);  u.w = h2u(v1.z, v1.w);
            *(uint4*)(HP + (it ? csoff1 : csoff0)) = u;
        }
#pragma unroll
        for (int it = 0; it < 2; ++it) {
            int r = it ? cr1 : cr0, gg = it ? cg1 : cg0;
            const float* p = obs + (size_t)(row0 + r) * 256 + gg * 8;
            pre[it][0] = *(const float4*)p;
            pre[it][1] = *(const float4*)(p + 4);
        }
    }

    for (int tile = local; tile < ntiles; tile += HCTA) {
        const int row0 = tile * 128;

        // ---- Phase B: fc1 GEMM, K=256 in 4 chunks of 64, double-buffered,
        //      1-deep cross-ks fragment pipeline ----
        float acc1[2][2][4];
#pragma unroll
        for (int st = 0; st < 2; ++st)
#pragma unroll
            for (int ng = 0; ng < 2; ++ng)
#pragma unroll
                for (int e = 0; e < 4; ++e) acc1[st][ng][e] = 0.0f;

        for (int kc = 0; kc < 4; ++kc) {
            {
                unsigned char* bb = sm + SM_X + (kc & 1) * 16384;
#pragma unroll
                for (int it = 0; it < 2; ++it) {
                    uint4 u;
                    u.x = h2u(pre[it][0].x, pre[it][0].y);  u.y = h2u(pre[it][0].z, pre[it][0].w);
                    u.z = h2u(pre[it][1].x, pre[it][1].y);  u.w = h2u(pre[it][1].z, pre[it][1].w);
                    *(uint4*)(bb + (it ? csoff1 : csoff0)) = u;
                }
            }
            if (kc < 3) {
#pragma unroll
                for (int it = 0; it < 2; ++it) {
                    int r = it ? cr1 : cr0, gg = it ? cg1 : cg0;
                    const float* p = obs + (size_t)(row0 + r) * 256 + (kc + 1) * 64 + gg * 8;
                    pre[it][0] = *(const float4*)p;
                    pre[it][1] = *(const float4*)(p + 4);
                }
            }
            __syncthreads();

            const uint32_t buf = Xu + (uint32_t)((kc & 1) * 16384);
            const uint32_t bth = Wu + (uint32_t)kc * TILE_B;
            const uint32_t btl = bth + 4 * TILE_B;

            uint32_t a[2][2][4], bh[2][4], bl[2][4];   // [parity][...]
            // preload ks=0 frags
#pragma unroll
            for (int st = 0; st < 2; ++st) {
                int row = rbase + 16 * st + rowa;
                ldsm4(a[0][st], buf + (uint32_t)(row * 128 + ((cca ^ (row & 7)) << 4)));
            }
            {
                uint32_t no = (uint32_t)(nB * 128 + ((binc ^ (nB & 7)) << 4));
                ldsm4(bh[0], bth + no);
                ldsm4(bl[0], btl + no);
            }
#pragma unroll
            for (int ks = 0; ks < 4; ++ks) {
                const int cur = ks & 1, nxt = cur ^ 1;
                if (ks < 3) {
#pragma unroll
                    for (int st = 0; st < 2; ++st) {
                        int row = rbase + 16 * st + rowa;
                        uint32_t ro = (uint32_t)(row * 128 + ((((ks + 1) * 2 + cca) ^ (row & 7)) << 4));
                        ldsm4(a[nxt][st], buf + ro);
                    }
                    int gin = (ks + 1) * 2 + binc;
                    uint32_t no = (uint32_t)(nB * 128 + ((gin ^ (nB & 7)) << 4));
                    ldsm4(bh[nxt], bth + no);
                    ldsm4(bl[nxt], btl + no);
                }
                mma16816(acc1[0][0], a[cur][0], &bh[cur][0]);  mma16816(acc1[1][0], a[cur][1], &bh[cur][0]);
                mma16816(acc1[0][1], a[cur][0], &bh[cur][2]);  mma16816(acc1[1][1], a[cur][1], &bh[cur][2]);
                mma16816(acc1[0][0], a[cur][0], &bl[cur][0]);  mma16816(acc1[1][0], a[cur][1], &bl[cur][0]);
                mma16816(acc1[0][1], a[cur][0], &bl[cur][2]);  mma16816(acc1[1][1], a[cur][1], &bl[cur][2]);
            }
        }
        __syncthreads();   // last chunk MMA done; X region reusable for the X plane

        // ---- Phase C (X plane write) fused with Pass 2 (H-side gate GEMMs) ----
#pragma unroll
        for (int st = 0; st < 2; ++st)
#pragma unroll
            for (int ng = 0; ng < 2; ++ng) {
                int col = nb0 + 8 * ng + 2 * tq;
                int ra = rbase + 16 * st + g;
                int rb = ra + 8;
                float x0 = ftanh(acc1[st][ng][0] + B1[col]);
                float x1 = ftanh(acc1[st][ng][1] + B1[col + 1]);
                float x2 = ftanh(acc1[st][ng][2] + B1[col]);
                float x3 = ftanh(acc1[st][ng][3] + B1[col + 1]);
                uint32_t offa = (uint32_t)(ra * 128 + (((col >> 3) ^ (ra & 7)) << 4) + (col & 7) * 2);
                uint32_t offb = (uint32_t)(rb * 128 + (((col >> 3) ^ (rb & 7)) << 4) + (col & 7) * 2);
                *(uint32_t*)(XP + offa) = h2u(x0, x1);
                *(uint32_t*)(XP + offb) = h2u(x2, x3);
            }

        float ar[2][2][4], az[2][2][4], anh[2][2][4];
#pragma unroll
        for (int st = 0; st < 2; ++st)
#pragma unroll
            for (int ng = 0; ng < 2; ++ng)
#pragma unroll
                for (int e = 0; e < 4; ++e) { ar[st][ng][e] = az[st][ng][e] = anh[st][ng][e] = 0.0f; }

#pragma unroll
        for (int ks = 0; ks < 4; ++ks) {
            uint32_t ah[2][4];
#pragma unroll
            for (int st = 0; st < 2; ++st) {
                int row = rbase + 16 * st + rowa;
                uint32_t ro = (uint32_t)(row * 128 + (((ks * 2 + cca) ^ (row & 7)) << 4));
                ldsm4(ah[st], Hu + ro);
            }
            int gin = ks * 2 + binc;
            uint32_t no = (uint32_t)(nB * 128 + ((gin ^ (nB & 7)) << 4));
            uint32_t brh[4], bzh[4], bnh_[4], brl[4], bzl[4], bnl[4];
            ldsm4(brh,  Wu + 14 * TILE_B + no);
            ldsm4(bzh,  Wu + 15 * TILE_B + no);
            ldsm4(bnh_, Wu + 16 * TILE_B + no);
            ldsm4(brl,  Wu + 17 * TILE_B + no);
            ldsm4(bzl,  Wu + 18 * TILE_B + no);
            ldsm4(bnl,  Wu + 19 * TILE_B + no);
#pragma unroll
            for (int ng = 0; ng < 2; ++ng) {
                mma16816(ar[0][ng],  ah[0], &brh[ng * 2]);  mma16816(ar[1][ng],  ah[1], &brh[ng * 2]);
                mma16816(az[0][ng],  ah[0], &bzh[ng * 2]);  mma16816(az[1][ng],  ah[1], &bzh[ng * 2]);
                mma16816(anh[0][ng], ah[0], &bnh_[ng * 2]); mma16816(anh[1][ng], ah[1], &bnh_[ng * 2]);
                mma16816(ar[0][ng],  ah[0], &brl[ng * 2]);  mma16816(ar[1][ng],  ah[1], &brl[ng * 2]);
                mma16816(az[0][ng],  ah[0], &bzl[ng * 2]);  mma16816(az[1][ng],  ah[1], &bzl[ng * 2]);
                mma16816(anh[0][ng], ah[0], &bnl[ng * 2]);  mma16816(anh[1][ng], ah[1], &bnl[ng * 2]);
            }
        }
        // X visibility only needs the 4 warps sharing this ms (they wrote rows rbase..rbase+32)
        GROUP_BAR(1 + ms);

        // ---- Pass 1: X-side gate GEMMs (slots 8..13) ----
        float ani[2][2][4];
#pragma unroll
        for (int st = 0; st < 2; ++st)
#pragma unroll
            for (int ng = 0; ng < 2; ++ng)
#pragma unroll
                for (int e = 0; e < 4; ++e) ani[st][ng][e] = 0.0f;

#pragma unroll
        for (int ks = 0; ks < 4; ++ks) {
            uint32_t ax[2][4];
#pragma unroll
            for (int st = 0; st < 2; ++st) {
                int row = rbase + 16 * st + rowa;
                uint32_t ro = (uint32_t)(row * 128 + (((ks * 2 + cca) ^ (row & 7)) << 4));
                ldsm4(ax[st], Xu + ro);
            }
            int gin = ks * 2 + binc;
            uint32_t no = (uint32_t)(nB * 128 + ((gin ^ (nB & 7)) << 4));
            uint32_t brh[4], bzh[4], bnh_[4], brl[4], bzl[4], bnl[4];
            ldsm4(brh,  Wu + 8  * TILE_B + no);
            ldsm4(bzh,  Wu + 9  * TILE_B + no);
            ldsm4(bnh_, Wu + 10 * TILE_B + no);
            ldsm4(brl,  Wu + 11 * TILE_B + no);
            ldsm4(bzl,  Wu + 12 * TILE_B + no);
            ldsm4(bnl,  Wu + 13 * TILE_B + no);
#pragma unroll
            for (int ng = 0; ng < 2; ++ng) {
                mma16816(ar[0][ng],  ax[0], &brh[ng * 2]);  mma16816(ar[1][ng],  ax[1], &brh[ng * 2]);
                mma16816(az[0][ng],  ax[0], &bzh[ng * 2]);  mma16816(az[1][ng],  ax[1], &bzh[ng * 2]);
                mma16816(ani[0][ng], ax[0], &bnh_[ng * 2]); mma16816(ani[1][ng], ax[1], &bnh_[ng * 2]);
                mma16816(ar[0][ng],  ax[0], &brl[ng * 2]);  mma16816(ar[1][ng],  ax[1], &brl[ng * 2]);
                mma16816(az[0][ng],  ax[0], &bzl[ng * 2]);  mma16816(az[1][ng],  ax[1], &bzl[ng * 2]);
                mma16816(ani[0][ng], ax[0], &bnl[ng * 2]);  mma16816(ani[1][ng], ax[1], &bnl[ng * 2]);
            }
        }
        __syncthreads();   // all X/H plane reads done (VP overlay + H-plane reuse safe)

        // ---- fused interval: epilogue(t) ∥ H-plane(t+1) ∥ obs prefetch(t+1) ----
        const int  ntile = tile + HCTA;
        const bool have_next = (ntile < ntiles);
        const int  nrow0 = ntile * 128;

        float4 nh[2][2];
        if (have_next) {
#pragma unroll
            for (int it = 0; it < 2; ++it) {
                int r = it ? cr1 : cr0, gg = it ? cg1 : cg0;
                const float* p = hin + (size_t)(nrow0 + r) * 64 + gg * 8;
                nh[it][0] = *(const float4*)p;
                nh[it][1] = *(const float4*)(p + 4);
            }
        }

        // batch hold + mask loads (gmem, L2-hot)
        float2 hold[2][2][2];
        int mk[4];
#pragma unroll
        for (int st = 0; st < 2; ++st) {
            mk[st * 2]     = mask[row0 + rbase + 16 * st + g];
            mk[st * 2 + 1] = mask[row0 + rbase + 16 * st + g + 8];
#pragma unroll
            for (int ng = 0; ng < 2; ++ng) {
                int cb = nb0 + 8 * ng + 2 * tq;
#pragma unroll
                for (int half = 0; half < 2; ++half) {
                    int row = rbase + 16 * st + g + 8 * half;
                    hold[st][ng][half] = *(const float2*)(hin + (size_t)(row0 + row) * 64 + cb);
                }
            }
        }

        float vp[4] = {0.0f, 0.0f, 0.0f, 0.0f};
#pragma unroll
        for (int st = 0; st < 2; ++st)
#pragma unroll
            for (int ng = 0; ng < 2; ++ng) {
                int cb = nb0 + 8 * ng + 2 * tq;
#pragma unroll
                for (int half = 0; half < 2; ++half) {
                    int row = rbase + 16 * st + g + 8 * half;
                    int m = mk[st * 2 + half];
                    float2 hv;
#pragma unroll
                    for (int e2 = 0; e2 < 2; ++e2) {
                        int e = 2 * half + e2;
                        int c = cb + e2;
                        float rr = fsigm(ar[st][ng][e] + BRZ[c]);
                        float zz = fsigm(az[st][ng][e] + BRZ[64 + c]);
                        float nn = ftanh(ani[st][ng][e] + BNI[c] +
                                         rr * (anh[st][ng][e] + BNH[c]));
                        float ho = e2 ? hold[st][ng][half].y : hold[st][ng][half].x;
                        float hg = (1.0f - zz) * nn + zz * ho;
                        float hn = m ? hg : ho;
                        if (e2) hv.y = hn; else hv.x = hn;
                        vp[st * 2 + half] += hn * W2[c];
                    }
                    *(float2*)(hout + (size_t)(row0 + row) * 64 + cb) = hv;
                }
            }

        // next-tile obs chunk0 prefetch (overlaps reduce + H-plane conversion)
        if (have_next) {
#pragma unroll
            for (int it = 0; it < 2; ++it) {
                int r = it ? cr1 : cr0, gg = it ? cg1 : cg0;
                const float* p = obs + (size_t)(nrow0 + r) * 256 + gg * 8;
                pre[it][0] = *(const float4*)p;
                pre[it][1] = *(const float4*)(p + 4);
            }
        }

#pragma unroll
        for (int off = 1; off <= 2; off <<= 1)
#pragma unroll
            for (int q = 0; q < 4; ++q) vp[q] += __shfl_xor_sync(0xffffffffu, vp[q], off);
        if (tq == 0) {
#pragma unroll
            for (int st = 0; st < 2; ++st) {
                VP[(rbase + 16 * st + g) * 4 + nq]     = vp[st * 2];
                VP[(rbase + 16 * st + g + 8) * 4 + nq] = vp[st * 2 + 1];
            }
        }

        // H plane(t+1): convert + store (H plane free since pass2)
        if (have_next) {
#pragma unroll
            for (int it = 0; it < 2; ++it) {
                uint4 u;
                u.x = h2u(nh[it][0].x, nh[it][0].y);  u.y = h2u(nh[it][0].z, nh[it][0].w);
                u.z = h2u(nh[it][1].x, nh[it][1].y);  u.w = h2u(nh[it][1].z, nh[it][1].w);
                *(uint4*)(HP + (it ? csoff1 : csoff0)) = u;
            }
        }
        __syncthreads();   // VP visible; H plane(t+1) ready

        if (tid < 128)
            vout[row0 + tid] = VP[tid * 4] + VP[tid * 4 + 1] + VP[tid * 4 + 2] + VP[tid * 4 + 3] + bias2;
    }
}

// ---------------- launch ----------------
extern "C" void kernel_launch(void* const* d_in, const int* in_sizes, int n_in,
                              void* d_out, int out_size) {
    const float* obs = (const float*)d_in[0];
    const float* h1  = (const float*)d_in[1];
    const float* h2  = (const float*)d_in[2];
    const int*   msk = (const int*)d_in[3];

    const int B = in_sizes[1] / 64;   // 262144
    const int ntiles = B / 128;       // 2048

    float* out = (float*)d_out;
    float* v1  = out;
    float* v2  = out + (size_t)B;
    float* ho1 = out + 2 * (size_t)B;
    float* ho2 = ho1 + (size_t)B * 64;

    convert_weights_kernel<<<160, 256>>>(
        (const float*)d_in[4],  (const float*)d_in[6],  (const float*)d_in[7],
        (const float*)d_in[12], (const float*)d_in[14], (const float*)d_in[15]);

    cudaFuncSetAttribute(gru_hmma_kernel,
                         cudaFuncAttributeMaxDynamicSharedMemorySize, SMEM_TOTAL);

    gru_hmma_kernel<<<NCTA, NT, SMEM_TOTAL>>>(
        obs, h1, h2, msk,
        (const float*)d_in[8],  (const float*)d_in[9],
        (const float*)d_in[5],  (const float*)d_in[10], (const float*)d_in[11],
        (const float*)d_in[16], (const float*)d_in[17],
        (const float*)d_in[13], (const float*)d_in[18], (const float*)d_in[19],
        v1, v2, ho1, ho2, ntiles);
}

// round 16
// speedup vs baseline: 1.5810x; 1.3198x over previous
#include <cuda_runtime.h>
#include <cuda_fp16.h>
#include <stdint.h>

#define NT 512
#define NCTA 148
#define HCTA 74

// ---------------- math helpers ----------------
__device__ __forceinline__ float fsigm(float x) { return __fdividef(1.0f, 1.0f + __expf(-x)); }
__device__ __forceinline__ float ftanh(float x) {
    return 1.0f - __fdividef(2.0f, __expf(2.0f * x) + 1.0f);
}
__device__ __forceinline__ uint32_t h2u(float a, float b) {   // lo=a, hi=b
    __half2 h = __floats2half2_rn(a, b);
    return *(uint32_t*)&h;
}
__device__ __forceinline__ uint32_t smem_u32(const void* p) {
    uint32_t a;
    asm("{ .reg .u64 t; cvta.to.shared.u64 t, %1; cvt.u32.u64 %0, t; }" : "=r"(a) : "l"(p));
    return a;
}

// ---------------- mma (fp16 in, fp32 acc) + ldmatrix ----------------
__device__ __forceinline__ void mma16816(float* c, const uint32_t* a, const uint32_t* b) {
    asm volatile(
        "mma.sync.aligned.m16n8k16.row.col.f32.f16.f16.f32 "
        "{%0,%1,%2,%3}, {%4,%5,%6,%7}, {%8,%9}, {%0,%1,%2,%3};"
        : "+f"(c[0]), "+f"(c[1]), "+f"(c[2]), "+f"(c[3])
        : "r"(a[0]), "r"(a[1]), "r"(a[2]), "r"(a[3]), "r"(b[0]), "r"(b[1]));
}
__device__ __forceinline__ void ldsm4(uint32_t* d, uint32_t addr) {
    asm volatile("ldmatrix.sync.aligned.m8n8.x4.shared.b16 {%0,%1,%2,%3}, [%4];"
                 : "=r"(d[0]), "=r"(d[1]), "=r"(d[2]), "=r"(d[3]) : "r"(addr));
}
#define GROUP_BAR(id) asm volatile("bar.sync %0, 128;" :: "r"(id) : "memory")

// ---------------- weight scratch: swizzled [64][64] fp16 tiles, 8KB each ------
// 10 tiles per stream: 0-3 fc1(kc), 4=ih_r 5=ih_z 6=ih_n, 7=hh_r 8=hh_z 9=hh_n
#define TILE_B 8192
#define TILE_H 4096
__device__ __align__(16) __half g_wt[2][10][TILE_H];

__global__ void convert_weights_kernel(
    const float* __restrict__ fc1a, const float* __restrict__ wiha, const float* __restrict__ whha,
    const float* __restrict__ fc1b, const float* __restrict__ wihb, const float* __restrict__ whhb)
{
    int tid = blockIdx.x * blockDim.x + threadIdx.x;
    int stride = gridDim.x * blockDim.x;
    for (int s = 0; s < 2; ++s) {
        const float* fc1 = s ? fc1b : fc1a;
        const float* wih = s ? wihb : wiha;
        const float* whh = s ? whhb : whha;
        for (int e = tid; e < 40960; e += stride) {
            float v; int th, n, k;
            if (e < 16384) {                        // fc1 [64,256] -> tiles 0..3
                n = e >> 8; int kf = e & 255; int kc = kf >> 6; k = kf & 63;
                v = fc1[e]; th = kc;
            } else if (e < 28672) {                 // wih [192,64] -> tiles 4..6
                int e2 = e - 16384, j = e2 >> 6; k = e2 & 63; int gg = j >> 6; n = j & 63;
                v = wih[e2]; th = 4 + gg;
            } else {                                // whh [192,64] -> tiles 7..9
                int e2 = e - 28672, j = e2 >> 6; k = e2 & 63; int gg = j >> 6; n = j & 63;
                v = whh[e2]; th = 7 + gg;
            }
            uint32_t off = n * 64 + (((k >> 3) ^ (n & 7)) << 3) + (k & 7);
            g_wt[s][th][off] = __float2half_rn(v);
        }
    }
}

// ---------------- smem layout (bytes) ----------------
#define SM_W    0                 // 10 tiles = 81920
#define SM_X    81920             // Phase B: buf0 @+0 (16KB), buf1 @+16384 (16KB)
                                  // Phase C/E: X plane @+0 (16KB); VP @+24576
#define SM_H    114688            // H plane [128 rows][128 B] = 16KB
#define SM_BRZ  131072            // float[128]: folded r,z biases
#define SM_BNI  131584            // float[64]
#define SM_BNH  131840            // float[64]
#define SM_B1   132096            // float[64]
#define SM_W2   132352            // float[64]
#define SMEM_TOTAL 132608

__global__ __launch_bounds__(NT, 1)
void gru_hmma_kernel(
    const float* __restrict__ obs, const float* __restrict__ h1, const float* __restrict__ h2,
    const int* __restrict__ mask,
    const float* __restrict__ bih1, const float* __restrict__ bhh1,
    const float* __restrict__ bfc1_1, const float* __restrict__ wfc2_1, const float* __restrict__ bfc2_1,
    const float* __restrict__ bih2, const float* __restrict__ bhh2,
    const float* __restrict__ bfc1_2, const float* __restrict__ wfc2_2, const float* __restrict__ bfc2_2,
    float* __restrict__ v1, float* __restrict__ v2,
    float* __restrict__ ho1, float* __restrict__ ho2,
    int ntiles)
{
    extern __shared__ __align__(16) unsigned char sm[];
    unsigned char* XP = sm + SM_X;
    unsigned char* HP = sm + SM_H;
    float* VP  = (float*)(sm + SM_X + 24576);
    float* BRZ = (float*)(sm + SM_BRZ);
    float* BNI = (float*)(sm + SM_BNI);
    float* BNH = (float*)(sm + SM_BNH);
    float* B1  = (float*)(sm + SM_B1);
    float* W2  = (float*)(sm + SM_W2);

    const int tid  = threadIdx.x;
    const int lane = tid & 31;
    const int wid  = tid >> 5;
    const int g    = lane >> 2;
    const int tq   = lane & 3;

    const int ms  = wid & 3;
    const int nq  = wid >> 2;
    const int rbase = 32 * ms;
    const int nb0   = 16 * nq;

    const int rowa = (lane & 7) + 8 * ((lane >> 3) & 1);
    const int cca  = lane >> 4;
    const int nB   = nb0 + ((lane >> 4) << 3) + (lane & 7);
    const int binc = (lane >> 3) & 1;

    const uint32_t smb = smem_u32(sm);
    const uint32_t Wu  = smb + SM_W;
    const uint32_t Xu  = smb + SM_X;
    const uint32_t Hu  = smb + SM_H;

    const int stream = (blockIdx.x >= HCTA) ? 1 : 0;
    const int local  = blockIdx.x - HCTA * stream;

    const float* hin = stream ? h2 : h1;
    const float* bih = stream ? bih2 : bih1;
    const float* bhh = stream ? bhh2 : bhh1;
    const float* bf1 = stream ? bfc1_2 : bfc1_1;
    const float* wf2 = stream ? wfc2_2 : wfc2_1;
    const float* bf2 = stream ? bfc2_2 : bfc2_1;
    float* vout = stream ? v2 : v1;
    float* hout = stream ? ho2 : ho1;

    const int cr0 = tid >> 3,        cg0 = tid & 7;
    const int cr1 = (tid + NT) >> 3, cg1 = (tid + NT) & 7;
    const uint32_t csoff0 = (uint32_t)(cr0 * 128 + ((cg0 ^ (cr0 & 7)) << 4));
    const uint32_t csoff1 = (uint32_t)(cr1 * 128 + ((cg1 ^ (cr1 & 7)) << 4));

    // ---- one-time: all 10 weight tiles + biases into smem ----
    {
        const int4* src = (const int4*)&g_wt[stream][0][0];
        int4* dst = (int4*)sm;
        for (int i = tid; i < (10 * TILE_B) / 16; i += NT) dst[i] = src[i];
    }
    if (tid < 128) BRZ[tid] = bih[tid] + bhh[tid];
    else if (tid < 192) BNI[tid - 128] = bih[tid];
    else if (tid < 256) BNH[tid - 192] = bhh[tid - 64];
    if (tid < 64) { B1[tid] = bf1[tid]; W2[tid] = wf2[tid]; }
    const float bias2 = bf2[0];
    __syncthreads();

    // ---- prologue: first tile H plane + obs chunk0 prefetch ----
    float4 pre[2][2];
    {
        const int row0 = local * 128;
#pragma unroll
        for (int it = 0; it < 2; ++it) {
            int r = it ? cr1 : cr0, gg = it ? cg1 : cg0;
            const float* p = hin + (size_t)(row0 + r) * 64 + gg * 8;
            float4 v0 = *(const float4*)p;
            float4 v1 = *(const float4*)(p + 4);
            uint4 u;
            u.x = h2u(v0.x, v0.y);  u.y = h2u(v0.z, v0.w);
            u.z = h2u(v1.x, v1.y);  u.w = h2u(v1.z, v1.w);
            *(uint4*)(HP + (it ? csoff1 : csoff0)) = u;
        }
#pragma unroll
        for (int it = 0; it < 2; ++it) {
            int r = it ? cr1 : cr0, gg = it ? cg1 : cg0;
            const float* p = obs + (size_t)(row0 + r) * 256 + gg * 8;
            pre[it][0] = *(const float4*)p;
            pre[it][1] = *(const float4*)(p + 4);
        }
    }

    for (int tile = local; tile < ntiles; tile += HCTA) {
        const int row0 = tile * 128;

        // ---- Phase B: fc1 GEMM, K=256 in 4 chunks of 64, double-buffered,
        //      1-deep cross-ks fragment pipeline ----
        float acc1[2][2][4];
#pragma unroll
        for (int st = 0; st < 2; ++st)
#pragma unroll
            for (int ng = 0; ng < 2; ++ng)
#pragma unroll
                for (int e = 0; e < 4; ++e) acc1[st][ng][e] = 0.0f;

        for (int kc = 0; kc < 4; ++kc) {
            {
                unsigned char* bb = sm + SM_X + (kc & 1) * 16384;
#pragma unroll
                for (int it = 0; it < 2; ++it) {
                    uint4 u;
                    u.x = h2u(pre[it][0].x, pre[it][0].y);  u.y = h2u(pre[it][0].z, pre[it][0].w);
                    u.z = h2u(pre[it][1].x, pre[it][1].y);  u.w = h2u(pre[it][1].z, pre[it][1].w);
                    *(uint4*)(bb + (it ? csoff1 : csoff0)) = u;
                }
            }
            if (kc < 3) {
#pragma unroll
                for (int it = 0; it < 2; ++it) {
                    int r = it ? cr1 : cr0, gg = it ? cg1 : cg0;
                    const float* p = obs + (size_t)(row0 + r) * 256 + (kc + 1) * 64 + gg * 8;
                    pre[it][0] = *(const float4*)p;
                    pre[it][1] = *(const float4*)(p + 4);
                }
            }
            __syncthreads();

            const uint32_t buf = Xu + (uint32_t)((kc & 1) * 16384);
            const uint32_t bth = Wu + (uint32_t)kc * TILE_B;

            uint32_t a[2][2][4], bh[2][4];   // [parity][...]
#pragma unroll
            for (int st = 0; st < 2; ++st) {
                int row = rbase + 16 * st + rowa;
                ldsm4(a[0][st], buf + (uint32_t)(row * 128 + ((cca ^ (row & 7)) << 4)));
            }
            ldsm4(bh[0], bth + (uint32_t)(nB * 128 + ((binc ^ (nB & 7)) << 4)));
#pragma unroll
            for (int ks = 0; ks < 4; ++ks) {
                const int cur = ks & 1, nxt = cur ^ 1;
                if (ks < 3) {
#pragma unroll
                    for (int st = 0; st < 2; ++st) {
                        int row = rbase + 16 * st + rowa;
                        uint32_t ro = (uint32_t)(row * 128 + ((((ks + 1) * 2 + cca) ^ (row & 7)) << 4));
                        ldsm4(a[nxt][st], buf + ro);
                    }
                    int gin = (ks + 1) * 2 + binc;
                    ldsm4(bh[nxt], bth + (uint32_t)(nB * 128 + ((gin ^ (nB & 7)) << 4)));
                }
                mma16816(acc1[0][0], a[cur][0], &bh[cur][0]);  mma16816(acc1[1][0], a[cur][1], &bh[cur][0]);
                mma16816(acc1[0][1], a[cur][0], &bh[cur][2]);  mma16816(acc1[1][1], a[cur][1], &bh[cur][2]);
            }
        }
        __syncthreads();   // last chunk MMA done; X region reusable for the X plane

        // ---- Phase C (X plane write) fused with Pass 2 (H-side gate GEMMs) ----
#pragma unroll
        for (int st = 0; st < 2; ++st)
#pragma unroll
            for (int ng = 0; ng < 2; ++ng) {
                int col = nb0 + 8 * ng + 2 * tq;
                int ra = rbase + 16 * st + g;
                int rb = ra + 8;
                float x0 = ftanh(acc1[st][ng][0] + B1[col]);
                float x1 = ftanh(acc1[st][ng][1] + B1[col + 1]);
                float x2 = ftanh(acc1[st][ng][2] + B1[col]);
                float x3 = ftanh(acc1[st][ng][3] + B1[col + 1]);
                uint32_t offa = (uint32_t)(ra * 128 + (((col >> 3) ^ (ra & 7)) << 4) + (col & 7) * 2);
                uint32_t offb = (uint32_t)(rb * 128 + (((col >> 3) ^ (rb & 7)) << 4) + (col & 7) * 2);
                *(uint32_t*)(XP + offa) = h2u(x0, x1);
                *(uint32_t*)(XP + offb) = h2u(x2, x3);
            }

        float ar[2][2][4], az[2][2][4], anh[2][2][4];
#pragma unroll
        for (int st = 0; st < 2; ++st)
#pragma unroll
            for (int ng = 0; ng < 2; ++ng)
#pragma unroll
                for (int e = 0; e < 4; ++e) { ar[st][ng][e] = az[st][ng][e] = anh[st][ng][e] = 0.0f; }

#pragma unroll
        for (int ks = 0; ks < 4; ++ks) {
            uint32_t ah[2][4];
#pragma unroll
            for (int st = 0; st < 2; ++st) {
                int row = rbase + 16 * st + rowa;
                uint32_t ro = (uint32_t)(row * 128 + (((ks * 2 + cca) ^ (row & 7)) << 4));
                ldsm4(ah[st], Hu + ro);
            }
            int gin = ks * 2 + binc;
            uint32_t no = (uint32_t)(nB * 128 + ((gin ^ (nB & 7)) << 4));
            uint32_t br[4], bz[4], bn[4];
            ldsm4(br, Wu + 7 * TILE_B + no);
            ldsm4(bz, Wu + 8 * TILE_B + no);
            ldsm4(bn, Wu + 9 * TILE_B + no);
#pragma unroll
            for (int ng = 0; ng < 2; ++ng) {
                mma16816(ar[0][ng],  ah[0], &br[ng * 2]);  mma16816(ar[1][ng],  ah[1], &br[ng * 2]);
                mma16816(az[0][ng],  ah[0], &bz[ng * 2]);  mma16816(az[1][ng],  ah[1], &bz[ng * 2]);
                mma16816(anh[0][ng], ah[0], &bn[ng * 2]);  mma16816(anh[1][ng], ah[1], &bn[ng * 2]);
            }
        }
        // X visibility only needs the 4 warps sharing this ms
        GROUP_BAR(1 + ms);

        // ---- Pass 1: X-side gate GEMMs (slots 4..6) ----
        float ani[2][2][4];
#pragma unroll
        for (int st = 0; st < 2; ++st)
#pragma unroll
            for (int ng = 0; ng < 2; ++ng)
#pragma unroll
                for (int e = 0; e < 4; ++e) ani[st][ng][e] = 0.0f;

#pragma unroll
        for (int ks = 0; ks < 4; ++ks) {
            uint32_t ax[2][4];
#pragma unroll
            for (int st = 0; st < 2; ++st) {
                int row = rbase + 16 * st + rowa;
                uint32_t ro = (uint32_t)(row * 128 + (((ks * 2 + cca) ^ (row & 7)) << 4));
                ldsm4(ax[st], Xu + ro);
            }
            int gin = ks * 2 + binc;
            uint32_t no = (uint32_t)(nB * 128 + ((gin ^ (nB & 7)) << 4));
            uint32_t br[4], bz[4], bn[4];
            ldsm4(br, Wu + 4 * TILE_B + no);
            ldsm4(bz, Wu + 5 * TILE_B + no);
            ldsm4(bn, Wu + 6 * TILE_B + no);
#pragma unroll
            for (int ng = 0; ng < 2; ++ng) {
                mma16816(ar[0][ng],  ax[0], &br[ng * 2]);  mma16816(ar[1][ng],  ax[1], &br[ng * 2]);
                mma16816(az[0][ng],  ax[0], &bz[ng * 2]);  mma16816(az[1][ng],  ax[1], &bz[ng * 2]);
                mma16816(ani[0][ng], ax[0], &bn[ng * 2]);  mma16816(ani[1][ng], ax[1], &bn[ng * 2]);
            }
        }
        __syncthreads();   // all X/H plane reads done (VP overlay + H-plane reuse safe)

        // ---- fused interval: epilogue(t) ∥ H-plane(t+1) ∥ obs prefetch(t+1) ----
        const int  ntile = tile + HCTA;
        const bool have_next = (ntile < ntiles);
        const int  nrow0 = ntile * 128;

        float4 nh[2][2];
        if (have_next) {
#pragma unroll
            for (int it = 0; it < 2; ++it) {
                int r = it ? cr1 : cr0, gg = it ? cg1 : cg0;
                const float* p = hin + (size_t)(nrow0 + r) * 64 + gg * 8;
                nh[it][0] = *(const float4*)p;
                nh[it][1] = *(const float4*)(p + 4);
            }
        }

        float2 hold[2][2][2];
        int mk[4];
#pragma unroll
        for (int st = 0; st < 2; ++st) {
            mk[st * 2]     = mask[row0 + rbase + 16 * st + g];
            mk[st * 2 + 1] = mask[row0 + rbase + 16 * st + g + 8];
#pragma unroll
            for (int ng = 0; ng < 2; ++ng) {
                int cb = nb0 + 8 * ng + 2 * tq;
#pragma unroll
                for (int half = 0; half < 2; ++half) {
                    int row = rbase + 16 * st + g + 8 * half;
                    hold[st][ng][half] = *(const float2*)(hin + (size_t)(row0 + row) * 64 + cb);
                }
            }
        }

        float vp[4] = {0.0f, 0.0f, 0.0f, 0.0f};
#pragma unroll
        for (int st = 0; st < 2; ++st)
#pragma unroll
            for (int ng = 0; ng < 2; ++ng) {
                int cb = nb0 + 8 * ng + 2 * tq;
#pragma unroll
                for (int half = 0; half < 2; ++half) {
                    int row = rbase + 16 * st + g + 8 * half;
                    int m = mk[st * 2 + half];
                    float2 hv;
#pragma unroll
                    for (int e2 = 0; e2 < 2; ++e2) {
                        int e = 2 * half + e2;
                        int c = cb + e2;
                        float rr = fsigm(ar[st][ng][e] + BRZ[c]);
                        float zz = fsigm(az[st][ng][e] + BRZ[64 + c]);
                        float nn = ftanh(ani[st][ng][e] + BNI[c] +
                                         rr * (anh[st][ng][e] + BNH[c]));
                        float ho = e2 ? hold[st][ng][half].y : hold[st][ng][half].x;
                        float hg = (1.0f - zz) * nn + zz * ho;
                        float hn = m ? hg : ho;
                        if (e2) hv.y = hn; else hv.x = hn;
                        vp[st * 2 + half] += hn * W2[c];
                    }
                    *(float2*)(hout + (size_t)(row0 + row) * 64 + cb) = hv;
                }
            }

        // next-tile obs chunk0 prefetch (overlaps reduce + H-plane conversion)
        if (have_next) {
#pragma unroll
            for (int it = 0; it < 2; ++it) {
                int r = it ? cr1 : cr0, gg = it ? cg1 : cg0;
                const float* p = obs + (size_t)(nrow0 + r) * 256 + gg * 8;
                pre[it][0] = *(const float4*)p;
                pre[it][1] = *(const float4*)(p + 4);
            }
        }

#pragma unroll
        for (int off = 1; off <= 2; off <<= 1)
#pragma unroll
            for (int q = 0; q < 4; ++q) vp[q] += __shfl_xor_sync(0xffffffffu, vp[q], off);
        if (tq == 0) {
#pragma unroll
            for (int st = 0; st < 2; ++st) {
                VP[(rbase + 16 * st + g) * 4 + nq]     = vp[st * 2];
                VP[(rbase + 16 * st + g + 8) * 4 + nq] = vp[st * 2 + 1];
            }
        }

        // H plane(t+1): convert + store (H plane free since pass2)
        if (have_next) {
#pragma unroll
            for (int it = 0; it < 2; ++it) {
                uint4 u;
                u.x = h2u(nh[it][0].x, nh[it][0].y);  u.y = h2u(nh[it][0].z, nh[it][0].w);
                u.z = h2u(nh[it][1].x, nh[it][1].y);  u.w = h2u(nh[it][1].z, nh[it][1].w);
                *(uint4*)(HP + (it ? csoff1 : csoff0)) = u;
            }
        }
        __syncthreads();   // VP visible; H plane(t+1) ready

        if (tid < 128)
            vout[row0 + tid] = VP[tid * 4] + VP[tid * 4 + 1] + VP[tid * 4 + 2] + VP[tid * 4 + 3] + bias2;
    }
}

// ---------------- launch ----------------
extern "C" void kernel_launch(void* const* d_in, const int* in_sizes, int n_in,
                              void* d_out, int out_size) {
    const float* obs = (const float*)d_in[0];
    const float* h1  = (const float*)d_in[1];
    const float* h2  = (const float*)d_in[2];
    const int*   msk = (const int*)d_in[3];

    const int B = in_sizes[1] / 64;   // 262144
    const int ntiles = B / 128;       // 2048

    float* out = (float*)d_out;
    float* v1  = out;
    float* v2  = out + (size_t)B;
    float* ho1 = out + 2 * (size_t)B;
    float* ho2 = ho1 + (size_t)B * 64;

    convert_weights_kernel<<<160, 256>>>(
        (const float*)d_in[4],  (const float*)d_in[6],  (const float*)d_in[7],
        (const float*)d_in[12], (const float*)d_in[14], (const float*)d_in[15]);

    cudaFuncSetAttribute(gru_hmma_kernel,
                         cudaFuncAttributeMaxDynamicSharedMemorySize, SMEM_TOTAL);

    gru_hmma_kernel<<<NCTA, NT, SMEM_TOTAL>>>(
        obs, h1, h2, msk,
        (const float*)d_in[8],  (const float*)d_in[9],
        (const float*)d_in[5],  (const float*)d_in[10], (const float*)d_in[11],
        (const float*)d_in[16], (const float*)d_in[17],
        (const float*)d_in[13], (const float*)d_in[18], (const float*)d_in[19],
        v1, v2, ho1, ho2, ntiles);
}

// round 17
// speedup vs baseline: 1.6463x; 1.0413x over previous
#include <cuda_runtime.h>
#include <cuda_fp16.h>
#include <stdint.h>

#define NT 256
#define NLOC 148          // CTAs per stream
#define NCTA (2 * NLOC)   // total grid

// ---------------- math helpers ----------------
__device__ __forceinline__ float fsigm(float x) { return __fdividef(1.0f, 1.0f + __expf(-x)); }
__device__ __forceinline__ float ftanh(float x) {
    return 1.0f - __fdividef(2.0f, __expf(2.0f * x) + 1.0f);
}
__device__ __forceinline__ uint32_t h2u(float a, float b) {   // lo=a, hi=b
    __half2 h = __floats2half2_rn(a, b);
    return *(uint32_t*)&h;
}
__device__ __forceinline__ uint32_t smem_u32(const void* p) {
    uint32_t a;
    asm("{ .reg .u64 t; cvta.to.shared.u64 t, %1; cvt.u32.u64 %0, t; }" : "=r"(a) : "l"(p));
    return a;
}

// ---------------- mma (fp16 in, fp32 acc) + ldmatrix ----------------
__device__ __forceinline__ void mma16816(float* c, const uint32_t* a, const uint32_t* b) {
    asm volatile(
        "mma.sync.aligned.m16n8k16.row.col.f32.f16.f16.f32 "
        "{%0,%1,%2,%3}, {%4,%5,%6,%7}, {%8,%9}, {%0,%1,%2,%3};"
        : "+f"(c[0]), "+f"(c[1]), "+f"(c[2]), "+f"(c[3])
        : "r"(a[0]), "r"(a[1]), "r"(a[2]), "r"(a[3]), "r"(b[0]), "r"(b[1]));
}
__device__ __forceinline__ void ldsm4(uint32_t* d, uint32_t addr) {
    asm volatile("ldmatrix.sync.aligned.m8n8.x4.shared.b16 {%0,%1,%2,%3}, [%4];"
                 : "=r"(d[0]), "=r"(d[1]), "=r"(d[2]), "=r"(d[3]) : "r"(addr));
}
#define GROUP_BAR(id) asm volatile("bar.sync %0, 128;" :: "r"(id) : "memory")

// ---------------- weight scratch: swizzled [64][64] fp16 tiles, 8KB each ------
// 10 tiles per stream: 0-3 fc1(kc), 4=ih_r 5=ih_z 6=ih_n, 7=hh_r 8=hh_z 9=hh_n
#define TILE_B 8192
#define TILE_H 4096
__device__ __align__(16) __half g_wt[2][10][TILE_H];

__global__ void convert_weights_kernel(
    const float* __restrict__ fc1a, const float* __restrict__ wiha, const float* __restrict__ whha,
    const float* __restrict__ fc1b, const float* __restrict__ wihb, const float* __restrict__ whhb)
{
    int tid = blockIdx.x * blockDim.x + threadIdx.x;
    int stride = gridDim.x * blockDim.x;
    for (int s = 0; s < 2; ++s) {
        const float* fc1 = s ? fc1b : fc1a;
        const float* wih = s ? wihb : wiha;
        const float* whh = s ? whhb : whha;
        for (int e = tid; e < 40960; e += stride) {
            float v; int th, n, k;
            if (e < 16384) {                        // fc1 [64,256] -> tiles 0..3
                n = e >> 8; int kf = e & 255; int kc = kf >> 6; k = kf & 63;
                v = fc1[e]; th = kc;
            } else if (e < 28672) {                 // wih [192,64] -> tiles 4..6
                int e2 = e - 16384, j = e2 >> 6; k = e2 & 63; int gg = j >> 6; n = j & 63;
                v = wih[e2]; th = 4 + gg;
            } else {                                // whh [192,64] -> tiles 7..9
                int e2 = e - 28672, j = e2 >> 6; k = e2 & 63; int gg = j >> 6; n = j & 63;
                v = whh[e2]; th = 7 + gg;
            }
            uint32_t off = n * 64 + (((k >> 3) ^ (n & 7)) << 3) + (k & 7);
            g_wt[s][th][off] = __float2half_rn(v);
        }
    }
}

// ---------------- smem layout (bytes), 64-row tile ----------------
#define SM_W    0                 // 10 tiles = 81920
#define SM_X    81920             // Phase B: buf0 @+0 (8KB), buf1 @+8192 (8KB)
                                  // Phase C/E: X plane @+0 (8KB); VP overlays buf1
#define SM_H    98304             // H plane [64 rows][128 B] = 8KB
#define SM_BRZ  106496            // float[128]: folded r,z biases
#define SM_BNI  107008            // float[64]
#define SM_BNH  107264            // float[64]
#define SM_B1   107520            // float[64]
#define SM_W2   107776            // float[64]
#define SMEM_TOTAL 108032

__global__ __launch_bounds__(NT, 2)
void gru_hmma_kernel(
    const float* __restrict__ obs, const float* __restrict__ h1, const float* __restrict__ h2,
    const int* __restrict__ mask,
    const float* __restrict__ bih1, const float* __restrict__ bhh1,
    const float* __restrict__ bfc1_1, const float* __restrict__ wfc2_1, const float* __restrict__ bfc2_1,
    const float* __restrict__ bih2, const float* __restrict__ bhh2,
    const float* __restrict__ bfc1_2, const float* __restrict__ wfc2_2, const float* __restrict__ bfc2_2,
    float* __restrict__ v1, float* __restrict__ v2,
    float* __restrict__ ho1, float* __restrict__ ho2,
    int ntiles)
{
    extern __shared__ __align__(16) unsigned char sm[];
    unsigned char* XP = sm + SM_X;          // X plane (post-B, buf0)
    unsigned char* HP = sm + SM_H;
    float* VP  = (float*)(sm + SM_X + 8192); // overlays buf1 (free post-pass1)
    float* BRZ = (float*)(sm + SM_BRZ);
    float* BNI = (float*)(sm + SM_BNI);
    float* BNH = (float*)(sm + SM_BNH);
    float* B1  = (float*)(sm + SM_B1);
    float* W2  = (float*)(sm + SM_W2);

    const int tid  = threadIdx.x;
    const int lane = tid & 31;
    const int wid  = tid >> 5;
    const int g    = lane >> 2;
    const int tq   = lane & 3;

    const int ms  = wid & 1;            // 32-row strip: rows 32ms..32ms+31
    const int nq  = wid >> 1;           // col quarter: cols 16nq..16nq+15
    const int rbase = 32 * ms;
    const int nb0   = 16 * nq;

    const int rowa = (lane & 7) + 8 * ((lane >> 3) & 1);
    const int cca  = lane >> 4;
    const int nB   = nb0 + ((lane >> 4) << 3) + (lane & 7);
    const int binc = (lane >> 3) & 1;

    const uint32_t smb = smem_u32(sm);
    const uint32_t Wu  = smb + SM_W;
    const uint32_t Xu  = smb + SM_X;
    const uint32_t Hu  = smb + SM_H;

    const int stream = blockIdx.x & 1;
    const int local  = blockIdx.x >> 1;

    const float* hin = stream ? h2 : h1;
    const float* bih = stream ? bih2 : bih1;
    const float* bhh = stream ? bhh2 : bhh1;
    const float* bf1 = stream ? bfc1_2 : bfc1_1;
    const float* wf2 = stream ? wfc2_2 : wfc2_1;
    const float* bf2 = stream ? bfc2_2 : bfc2_1;
    float* vout = stream ? v2 : v1;
    float* hout = stream ? ho2 : ho1;

    // conversion task: 64 rows x 8 granules = 512 tasks, 2 per thread
    const int cr0 = tid >> 3,         cg0 = tid & 7;          // rows 0..31
    const int cr1 = (tid + NT) >> 3,  cg1 = (tid + NT) & 7;   // rows 32..63
    const uint32_t csoff0 = (uint32_t)(cr0 * 128 + ((cg0 ^ (cr0 & 7)) << 4));
    const uint32_t csoff1 = (uint32_t)(cr1 * 128 + ((cg1 ^ (cr1 & 7)) << 4));

    // ---- one-time: all 10 weight tiles + biases into smem ----
    {
        const int4* src = (const int4*)&g_wt[stream][0][0];
        int4* dst = (int4*)sm;
        for (int i = tid; i < (10 * TILE_B) / 16; i += NT) dst[i] = src[i];
    }
    if (tid < 128) BRZ[tid] = bih[tid] + bhh[tid];
    else if (tid < 192) BNI[tid - 128] = bih[tid];
    else BNH[tid - 192] = bhh[tid - 64];
    if (tid < 64) { B1[tid] = bf1[tid]; W2[tid] = wf2[tid]; }
    const float bias2 = bf2[0];
    __syncthreads();

    // ---- prologue: first tile H plane + obs chunk0 prefetch ----
    float4 pre[2][2];
    {
        const int row0 = local * 64;
#pragma unroll
        for (int it = 0; it < 2; ++it) {
            int r = it ? cr1 : cr0, gg = it ? cg1 : cg0;
            const float* p = hin + (size_t)(row0 + r) * 64 + gg * 8;
            float4 v0 = *(const float4*)p;
            float4 v1 = *(const float4*)(p + 4);
            uint4 u;
            u.x = h2u(v0.x, v0.y);  u.y = h2u(v0.z, v0.w);
            u.z = h2u(v1.x, v1.y);  u.w = h2u(v1.z, v1.w);
            *(uint4*)(HP + (it ? csoff1 : csoff0)) = u;
        }
#pragma unroll
        for (int it = 0; it < 2; ++it) {
            int r = it ? cr1 : cr0, gg = it ? cg1 : cg0;
            const float* p = obs + (size_t)(row0 + r) * 256 + gg * 8;
            pre[it][0] = *(const float4*)p;
            pre[it][1] = *(const float4*)(p + 4);
        }
    }

    for (int tile = local; tile < ntiles; tile += NLOC) {
        const int row0 = tile * 64;

        // ---- Phase B: fc1 GEMM, K=256 in 4 chunks of 64, double-buffered,
        //      1-deep cross-ks fragment pipeline ----
        float acc1[2][2][4];
#pragma unroll
        for (int st = 0; st < 2; ++st)
#pragma unroll
            for (int ng = 0; ng < 2; ++ng)
#pragma unroll
                for (int e = 0; e < 4; ++e) acc1[st][ng][e] = 0.0f;

        for (int kc = 0; kc < 4; ++kc) {
            {
                unsigned char* bb = sm + SM_X + (kc & 1) * 8192;
#pragma unroll
                for (int it = 0; it < 2; ++it) {
                    uint4 u;
                    u.x = h2u(pre[it][0].x, pre[it][0].y);  u.y = h2u(pre[it][0].z, pre[it][0].w);
                    u.z = h2u(pre[it][1].x, pre[it][1].y);  u.w = h2u(pre[it][1].z, pre[it][1].w);
                    *(uint4*)(bb + (it ? csoff1 : csoff0)) = u;
                }
            }
            if (kc < 3) {
#pragma unroll
                for (int it = 0; it < 2; ++it) {
                    int r = it ? cr1 : cr0, gg = it ? cg1 : cg0;
                    const float* p = obs + (size_t)(row0 + r) * 256 + (kc + 1) * 64 + gg * 8;
                    pre[it][0] = *(const float4*)p;
                    pre[it][1] = *(const float4*)(p + 4);
                }
            }
            __syncthreads();

            const uint32_t buf = Xu + (uint32_t)((kc & 1) * 8192);
            const uint32_t bth = Wu + (uint32_t)kc * TILE_B;

            uint32_t a[2][2][4], bh[2][4];
#pragma unroll
            for (int st = 0; st < 2; ++st) {
                int row = rbase + 16 * st + rowa;
                ldsm4(a[0][st], buf + (uint32_t)(row * 128 + ((cca ^ (row & 7)) << 4)));
            }
            ldsm4(bh[0], bth + (uint32_t)(nB * 128 + ((binc ^ (nB & 7)) << 4)));
#pragma unroll
            for (int ks = 0; ks < 4; ++ks) {
                const int cur = ks & 1, nxt = cur ^ 1;
                if (ks < 3) {
#pragma unroll
                    for (int st = 0; st < 2; ++st) {
                        int row = rbase + 16 * st + rowa;
                        uint32_t ro = (uint32_t)(row * 128 + ((((ks + 1) * 2 + cca) ^ (row & 7)) << 4));
                        ldsm4(a[nxt][st], buf + ro);
                    }
                    int gin = (ks + 1) * 2 + binc;
                    ldsm4(bh[nxt], bth + (uint32_t)(nB * 128 + ((gin ^ (nB & 7)) << 4)));
                }
                mma16816(acc1[0][0], a[cur][0], &bh[cur][0]);  mma16816(acc1[1][0], a[cur][1], &bh[cur][0]);
                mma16816(acc1[0][1], a[cur][0], &bh[cur][2]);  mma16816(acc1[1][1], a[cur][1], &bh[cur][2]);
            }
        }
        __syncthreads();   // last chunk MMA done; buf0 reusable for the X plane

        // ---- Phase C (X plane write, into buf0) fused with Pass 2 (H-side GEMMs) ----
#pragma unroll
        for (int st = 0; st < 2; ++st)
#pragma unroll
            for (int ng = 0; ng < 2; ++ng) {
                int col = nb0 + 8 * ng + 2 * tq;
                int ra = rbase + 16 * st + g;
                int rb = ra + 8;
                float x0 = ftanh(acc1[st][ng][0] + B1[col]);
                float x1 = ftanh(acc1[st][ng][1] + B1[col + 1]);
                float x2 = ftanh(acc1[st][ng][2] + B1[col]);
                float x3 = ftanh(acc1[st][ng][3] + B1[col + 1]);
                uint32_t offa = (uint32_t)(ra * 128 + (((col >> 3) ^ (ra & 7)) << 4) + (col & 7) * 2);
                uint32_t offb = (uint32_t)(rb * 128 + (((col >> 3) ^ (rb & 7)) << 4) + (col & 7) * 2);
                *(uint32_t*)(XP + offa) = h2u(x0, x1);
                *(uint32_t*)(XP + offb) = h2u(x2, x3);
            }

        float ar[2][2][4], az[2][2][4], anh[2][2][4];
#pragma unroll
        for (int st = 0; st < 2; ++st)
#pragma unroll
            for (int ng = 0; ng < 2; ++ng)
#pragma unroll
                for (int e = 0; e < 4; ++e) { ar[st][ng][e] = az[st][ng][e] = anh[st][ng][e] = 0.0f; }

#pragma unroll
        for (int ks = 0; ks < 4; ++ks) {
            uint32_t ah[2][4];
#pragma unroll
            for (int st = 0; st < 2; ++st) {
                int row = rbase + 16 * st + rowa;
                uint32_t ro = (uint32_t)(row * 128 + (((ks * 2 + cca) ^ (row & 7)) << 4));
                ldsm4(ah[st], Hu + ro);
            }
            int gin = ks * 2 + binc;
            uint32_t no = (uint32_t)(nB * 128 + ((gin ^ (nB & 7)) << 4));
            uint32_t br[4], bz[4], bn[4];
            ldsm4(br, Wu + 7 * TILE_B + no);
            ldsm4(bz, Wu + 8 * TILE_B + no);
            ldsm4(bn, Wu + 9 * TILE_B + no);
#pragma unroll
            for (int ng = 0; ng < 2; ++ng) {
                mma16816(ar[0][ng],  ah[0], &br[ng * 2]);  mma16816(ar[1][ng],  ah[1], &br[ng * 2]);
                mma16816(az[0][ng],  ah[0], &bz[ng * 2]);  mma16816(az[1][ng],  ah[1], &bz[ng * 2]);
                mma16816(anh[0][ng], ah[0], &bn[ng * 2]);  mma16816(anh[1][ng], ah[1], &bn[ng * 2]);
            }
        }
        // X visibility only needs the 4 warps sharing this ms (128 threads)
        GROUP_BAR(1 + ms);

        // ---- Pass 1: X-side gate GEMMs (slots 4..6) ----
        float ani[2][2][4];
#pragma unroll
        for (int st = 0; st < 2; ++st)
#pragma unroll
            for (int ng = 0; ng < 2; ++ng)
#pragma unroll
                for (int e = 0; e < 4; ++e) ani[st][ng][e] = 0.0f;

#pragma unroll
        for (int ks = 0; ks < 4; ++ks) {
            uint32_t ax[2][4];
#pragma unroll
            for (int st = 0; st < 2; ++st) {
                int row = rbase + 16 * st + rowa;
                uint32_t ro = (uint32_t)(row * 128 + (((ks * 2 + cca) ^ (row & 7)) << 4));
                ldsm4(ax[st], Xu + ro);
            }
            int gin = ks * 2 + binc;
            uint32_t no = (uint32_t)(nB * 128 + ((gin ^ (nB & 7)) << 4));
            uint32_t br[4], bz[4], bn[4];
            ldsm4(br, Wu + 4 * TILE_B + no);
            ldsm4(bz, Wu + 5 * TILE_B + no);
            ldsm4(bn, Wu + 6 * TILE_B + no);
#pragma unroll
            for (int ng = 0; ng < 2; ++ng) {
                mma16816(ar[0][ng],  ax[0], &br[ng * 2]);  mma16816(ar[1][ng],  ax[1], &br[ng * 2]);
                mma16816(az[0][ng],  ax[0], &bz[ng * 2]);  mma16816(az[1][ng],  ax[1], &bz[ng * 2]);
                mma16816(ani[0][ng], ax[0], &bn[ng * 2]);  mma16816(ani[1][ng], ax[1], &bn[ng * 2]);
            }
        }
        __syncthreads();   // all X/H plane reads done (VP overlay + H-plane reuse safe)

        // ---- fused interval: epilogue(t) ∥ H-plane(t+1) ∥ obs prefetch(t+1) ----
        const int  ntile = tile + NLOC;
        const bool have_next = (ntile < ntiles);
        const int  nrow0 = ntile * 64;

        float4 nh[2][2];
        if (have_next) {
#pragma unroll
            for (int it = 0; it < 2; ++it) {
                int r = it ? cr1 : cr0, gg = it ? cg1 : cg0;
                const float* p = hin + (size_t)(nrow0 + r) * 64 + gg * 8;
                nh[it][0] = *(const float4*)p;
                nh[it][1] = *(const float4*)(p + 4);
            }
        }

        float2 hold[2][2][2];
        int mk[4];
#pragma unroll
        for (int st = 0; st < 2; ++st) {
            mk[st * 2]     = mask[row0 + rbase + 16 * st + g];
            mk[st * 2 + 1] = mask[row0 + rbase + 16 * st + g + 8];
#pragma unroll
            for (int ng = 0; ng < 2; ++ng) {
                int cb = nb0 + 8 * ng + 2 * tq;
#pragma unroll
                for (int half = 0; half < 2; ++half) {
                    int row = rbase + 16 * st + g + 8 * half;
                    hold[st][ng][half] = *(const float2*)(hin + (size_t)(row0 + row) * 64 + cb);
                }
            }
        }

        float vp[4] = {0.0f, 0.0f, 0.0f, 0.0f};
#pragma unroll
        for (int st = 0; st < 2; ++st)
#pragma unroll
            for (int ng = 0; ng < 2; ++ng) {
                int cb = nb0 + 8 * ng + 2 * tq;
#pragma unroll
                for (int half = 0; half < 2; ++half) {
                    int row = rbase + 16 * st + g + 8 * half;
                    int m = mk[st * 2 + half];
                    float2 hv;
#pragma unroll
                    for (int e2 = 0; e2 < 2; ++e2) {
                        int e = 2 * half + e2;
                        int c = cb + e2;
                        float rr = fsigm(ar[st][ng][e] + BRZ[c]);
                        float zz = fsigm(az[st][ng][e] + BRZ[64 + c]);
                        float nn = ftanh(ani[st][ng][e] + BNI[c] +
                                         rr * (anh[st][ng][e] + BNH[c]));
                        float ho = e2 ? hold[st][ng][half].y : hold[st][ng][half].x;
                        float hg = (1.0f - zz) * nn + zz * ho;
                        float hn = m ? hg : ho;
                        if (e2) hv.y = hn; else hv.x = hn;
                        vp[st * 2 + half] += hn * W2[c];
                    }
                    *(float2*)(hout + (size_t)(row0 + row) * 64 + cb) = hv;
                }
            }

        // next-tile obs chunk0 prefetch (overlaps reduce + H-plane conversion)
        if (have_next) {
#pragma unroll
            for (int it = 0; it < 2; ++it) {
                int r = it ? cr1 : cr0, gg = it ? cg1 : cg0;
                const float* p = obs + (size_t)(nrow0 + r) * 256 + gg * 8;
                pre[it][0] = *(const float4*)p;
                pre[it][1] = *(const float4*)(p + 4);
            }
        }

#pragma unroll
        for (int off = 1; off <= 2; off <<= 1)
#pragma unroll
            for (int q = 0; q < 4; ++q) vp[q] += __shfl_xor_sync(0xffffffffu, vp[q], off);
        if (tq == 0) {
#pragma unroll
            for (int st = 0; st < 2; ++st) {
                VP[(rbase + 16 * st + g) * 4 + nq]     = vp[st * 2];
                VP[(rbase + 16 * st + g + 8) * 4 + nq] = vp[st * 2 + 1];
            }
        }

        // H plane(t+1): convert + store (H plane free since pass2)
        if (have_next) {
#pragma unroll
            for (int it = 0; it < 2; ++it) {
                uint4 u;
                u.x = h2u(nh[it][0].x, nh[it][0].y);  u.y = h2u(nh[it][0].z, nh[it][0].w);
                u.z = h2u(nh[it][1].x, nh[it][1].y);  u.w = h2u(nh[it][1].z, nh[it][1].w);
                *(uint4*)(HP + (it ? csoff1 : csoff0)) = u;
            }
        }
        __syncthreads();   // VP visible; H plane(t+1) ready

        if (tid < 64)
            vout[row0 + tid] = VP[tid * 4] + VP[tid * 4 + 1] + VP[tid * 4 + 2] + VP[tid * 4 + 3] + bias2;
    }
}

// ---------------- launch ----------------
extern "C" void kernel_launch(void* const* d_in, const int* in_sizes, int n_in,
                              void* d_out, int out_size) {
    const float* obs = (const float*)d_in[0];
    const float* h1  = (const float*)d_in[1];
    const float* h2  = (const float*)d_in[2];
    const int*   msk = (const int*)d_in[3];

    const int B = in_sizes[1] / 64;   // 262144
    const int ntiles = B / 64;        // 4096 per stream

    float* out = (float*)d_out;
    float* v1  = out;
    float* v2  = out + (size_t)B;
    float* ho1 = out + 2 * (size_t)B;
    float* ho2 = ho1 + (size_t)B * 64;

    convert_weights_kernel<<<160, 256>>>(
        (const float*)d_in[4],  (const float*)d_in[6],  (const float*)d_in[7],
        (const float*)d_in[12], (const float*)d_in[14], (const float*)d_in[15]);

    cudaFuncSetAttribute(gru_hmma_kernel,
                         cudaFuncAttributeMaxDynamicSharedMemorySize, SMEM_TOTAL);

    gru_hmma_kernel<<<NCTA, NT, SMEM_TOTAL>>>(
        obs, h1, h2, msk,
        (const float*)d_in[8],  (const float*)d_in[9],
        (const float*)d_in[5],  (const float*)d_in[10], (const float*)d_in[11],
        (const float*)d_in[16], (const float*)d_in[17],
        (const float*)d_in[13], (const float*)d_in[18], (const float*)d_in[19],
        v1, v2, ho1, ho2, ntiles);
}